// round 3
// baseline (speedup 1.0000x reference)
#include <cuda_runtime.h>
#include <math.h>
#include <stdint.h>

#define BATCH 32
#define NPTS  128
#define DIM   2048
#define HID   1024
#define MROWS (BATCH * NPTS)        // 4096

// ------------------------------ scratch ------------------------------------
__device__ float d_cost[BATCH * NPTS * NPTS];
__device__ float d_ns[BATCH * NPTS];
__device__ float d_nq[BATCH * NPTS];
__device__ int   d_perm[MROWS];
__device__ float d_h[2u * MROWS * HID];

// ------------------------------ norms --------------------------------------
__global__ void norm_kernel(const float* __restrict__ S, const float* __restrict__ Q) {
    int r = blockIdx.x;
    int tid = threadIdx.x;
    const float* srow = S + (size_t)r * DIM;
    const float* qrow = Q + (size_t)r * DIM;
    float s = 0.f, q = 0.f;
    for (int k = tid; k < DIM; k += 128) {
        float a = srow[k]; s = fmaf(a, a, s);
        float c = qrow[k]; q = fmaf(c, c, q);
    }
    for (int off = 16; off; off >>= 1) {
        s += __shfl_down_sync(0xffffffffu, s, off);
        q += __shfl_down_sync(0xffffffffu, q, off);
    }
    __shared__ float ss[4], qq[4];
    if ((tid & 31) == 0) { ss[tid >> 5] = s; qq[tid >> 5] = q; }
    __syncthreads();
    if (tid == 0) {
        d_ns[r] = sqrtf(ss[0] + ss[1] + ss[2] + ss[3]);
        d_nq[r] = sqrtf(qq[0] + qq[1] + qq[2] + qq[3]);
    }
}

// ------------------------------ cost GEMM ----------------------------------
__global__ void __launch_bounds__(256) cost_kernel(const float* __restrict__ S,
                                                   const float* __restrict__ Q) {
    constexpr int BK = 16, TM = 8, TN = 8;
    __shared__ float As[BK][NPTS];
    __shared__ float Bs[BK][NPTS];
    int b = blockIdx.x;
    const float* Sb = S + (size_t)b * NPTS * DIM;
    const float* Qb = Q + (size_t)b * NPTS * DIM;
    int tid = threadIdx.x;
    int aRow0 = tid >> 2, aK0 = (tid & 3) << 2;
    int aRow1 = aRow0 + 64;
    const float* Sr0 = Sb + (size_t)aRow0 * DIM + aK0;
    const float* Sr1 = Sb + (size_t)aRow1 * DIM + aK0;
    const float* Qr0 = Qb + (size_t)aRow0 * DIM + aK0;
    const float* Qr1 = Qb + (size_t)aRow1 * DIM + aK0;
    int tx = tid & 15, ty = tid >> 4;
    float acc[TM][TN];
#pragma unroll
    for (int m = 0; m < TM; m++)
#pragma unroll
        for (int n = 0; n < TN; n++) acc[m][n] = 0.f;

    for (int k0 = 0; k0 < DIM; k0 += BK) {
        float4 a0 = *(const float4*)(Sr0 + k0);
        float4 a1 = *(const float4*)(Sr1 + k0);
        float4 b0 = *(const float4*)(Qr0 + k0);
        float4 b1 = *(const float4*)(Qr1 + k0);
        __syncthreads();
        As[aK0 + 0][aRow0] = a0.x; As[aK0 + 1][aRow0] = a0.y;
        As[aK0 + 2][aRow0] = a0.z; As[aK0 + 3][aRow0] = a0.w;
        As[aK0 + 0][aRow1] = a1.x; As[aK0 + 1][aRow1] = a1.y;
        As[aK0 + 2][aRow1] = a1.z; As[aK0 + 3][aRow1] = a1.w;
        Bs[aK0 + 0][aRow0] = b0.x; Bs[aK0 + 1][aRow0] = b0.y;
        Bs[aK0 + 2][aRow0] = b0.z; Bs[aK0 + 3][aRow0] = b0.w;
        Bs[aK0 + 0][aRow1] = b1.x; Bs[aK0 + 1][aRow1] = b1.y;
        Bs[aK0 + 2][aRow1] = b1.z; Bs[aK0 + 3][aRow1] = b1.w;
        __syncthreads();
#pragma unroll
        for (int k = 0; k < BK; k++) {
            float a[TM], bb[TN];
#pragma unroll
            for (int m = 0; m < TM; m++) a[m] = As[k][ty * TM + m];
#pragma unroll
            for (int n = 0; n < TN; n++) bb[n] = Bs[k][tx * TN + n];
#pragma unroll
            for (int m = 0; m < TM; m++)
#pragma unroll
                for (int n = 0; n < TN; n++) acc[m][n] = fmaf(a[m], bb[n], acc[m][n]);
        }
    }
#pragma unroll
    for (int m = 0; m < TM; m++) {
        int r = ty * TM + m;
        float ni = d_ns[b * NPTS + r];
#pragma unroll
        for (int n = 0; n < TN; n++) {
            int c = tx * TN + n;
            float nj = d_nq[b * NPTS + c];
            d_cost[b * NPTS * NPTS + r * NPTS + c] = 1.0f - acc[m][n] / (ni * nj);
        }
    }
}

// ------------------------------ JV Hungarian --------------------------------
__global__ void lap_kernel() {
    int b = blockIdx.x;
    const float* cost = d_cost + b * NPTS * NPTS;
    __shared__ double u[NPTS + 1], v[NPTS + 1], minv[NPTS + 1];
    __shared__ int p[NPTS + 1], way[NPTS + 1];
    __shared__ unsigned char used[NPTS + 1];
    int lane = threadIdx.x;

    for (int j = lane; j <= NPTS; j += 32) { u[j] = 0.0; v[j] = 0.0; p[j] = 0; way[j] = 0; }
    __syncwarp();

    for (int i = 1; i <= NPTS; i++) {
        if (lane == 0) p[0] = i;
        for (int j = lane; j <= NPTS; j += 32) { minv[j] = INFINITY; used[j] = 0; }
        __syncwarp();
        int j0 = 0;
        for (int iter = 0; iter < NPTS + 8; ++iter) {
            if (lane == 0) used[j0] = 1;
            __syncwarp();
            int i0 = p[j0];
            double ui0 = u[i0];
            double best = INFINITY;
            int jbest = NPTS + 1;
#pragma unroll
            for (int t = 0; t < 4; t++) {
                int j = lane * 4 + 1 + t;
                if (!used[j]) {
                    double cur = (double)cost[(i0 - 1) * NPTS + (j - 1)] - ui0 - v[j];
                    if (cur < minv[j]) { minv[j] = cur; way[j] = j0; }
                    double m = minv[j];
                    if (m < best) { best = m; jbest = j; }
                }
            }
            for (int off = 16; off; off >>= 1) {
                double ob = __shfl_down_sync(0xffffffffu, best, off);
                int oj = __shfl_down_sync(0xffffffffu, jbest, off);
                if (ob < best || (ob == best && oj < jbest)) { best = ob; jbest = oj; }
            }
            double delta = __shfl_sync(0xffffffffu, best, 0);
            int j1 = __shfl_sync(0xffffffffu, jbest, 0);
            __syncwarp();
#pragma unroll
            for (int t = 0; t < 4; t++) {
                int j = lane * 4 + 1 + t;
                if (used[j]) { v[j] -= delta; u[p[j]] += delta; }
                else minv[j] -= delta;
            }
            if (lane == 0) { u[p[0]] += delta; v[0] -= delta; }
            __syncwarp();
            j0 = j1;
            if (p[j0] == 0) break;
        }
        if (lane == 0) {
            int jj = j0;
            while (jj) { int jn = way[jj]; p[jj] = p[jn]; jj = jn; }
        }
        __syncwarp();
    }
    for (int j = lane + 1; j <= NPTS; j += 32)
        d_perm[b * NPTS + (p[j] - 1)] = b * NPTS + (j - 1);
}

// ------------------------------ MLP GEMM ------------------------------------
__global__ void __launch_bounds__(256) gemm_kernel(
    const float* __restrict__ Xext, const float* __restrict__ W,
    float* __restrict__ Cext, const float* __restrict__ resid,
    int x_h,      // 0 = Xext, 1 = d_h half 0, 2 = d_h half 1
    int c_h,      // 0 = Cext, 1 = d_h half 0, 2 = d_h half 1
    int permX_on, int permR_on,
    int N, int K) {
    constexpr int BM = 128, BN = 128, BK = 16, TM = 8, TN = 8;
    __shared__ float As[BK][BM];
    __shared__ float Bs[BK][BN];
    const float* X = (x_h == 0) ? Xext : (d_h + (size_t)(x_h - 1) * MROWS * HID);
    float* C = (c_h == 0) ? Cext : (d_h + (size_t)(c_h - 1) * MROWS * HID);
    const int* permX = permX_on ? d_perm : nullptr;
    const int* permR = permR_on ? d_perm : nullptr;

    int tid = threadIdx.x;
    int bx = blockIdx.x, by = blockIdx.y;
    int aRow0 = tid >> 2, aK0 = (tid & 3) << 2;
    int aRow1 = aRow0 + 64;
    int g0 = by * BM + aRow0, g1 = by * BM + aRow1;
    int s0 = permX ? permX[g0] : g0;
    int s1 = permX ? permX[g1] : g1;
    const float* Xr0 = X + (size_t)s0 * K + aK0;
    const float* Xr1 = X + (size_t)s1 * K + aK0;
    const float* Wr0 = W + (size_t)(bx * BN + aRow0) * K + aK0;
    const float* Wr1 = W + (size_t)(bx * BN + aRow1) * K + aK0;
    int tx = tid & 15, ty = tid >> 4;
    float acc[TM][TN];
#pragma unroll
    for (int m = 0; m < TM; m++)
#pragma unroll
        for (int n = 0; n < TN; n++) acc[m][n] = 0.f;

    for (int k0 = 0; k0 < K; k0 += BK) {
        float4 a0 = *(const float4*)(Xr0 + k0);
        float4 a1 = *(const float4*)(Xr1 + k0);
        float4 b0 = *(const float4*)(Wr0 + k0);
        float4 b1 = *(const float4*)(Wr1 + k0);
        __syncthreads();
        As[aK0 + 0][aRow0] = a0.x; As[aK0 + 1][aRow0] = a0.y;
        As[aK0 + 2][aRow0] = a0.z; As[aK0 + 3][aRow0] = a0.w;
        As[aK0 + 0][aRow1] = a1.x; As[aK0 + 1][aRow1] = a1.y;
        As[aK0 + 2][aRow1] = a1.z; As[aK0 + 3][aRow1] = a1.w;
        Bs[aK0 + 0][aRow0] = b0.x; Bs[aK0 + 1][aRow0] = b0.y;
        Bs[aK0 + 2][aRow0] = b0.z; Bs[aK0 + 3][aRow0] = b0.w;
        Bs[aK0 + 0][aRow1] = b1.x; Bs[aK0 + 1][aRow1] = b1.y;
        Bs[aK0 + 2][aRow1] = b1.z; Bs[aK0 + 3][aRow1] = b1.w;
        __syncthreads();
#pragma unroll
        for (int k = 0; k < BK; k++) {
            float a[TM], bb[TN];
#pragma unroll
            for (int m = 0; m < TM; m++) a[m] = As[k][ty * TM + m];
#pragma unroll
            for (int n = 0; n < TN; n++) bb[n] = Bs[k][tx * TN + n];
#pragma unroll
            for (int m = 0; m < TM; m++)
#pragma unroll
                for (int n = 0; n < TN; n++) acc[m][n] = fmaf(a[m], bb[n], acc[m][n]);
        }
    }
    int row0 = by * BM + ty * TM, col0 = bx * BN + tx * TN;
#pragma unroll
    for (int m = 0; m < TM; m++) {
        int gr = row0 + m;
        const float* rr = nullptr;
        if (resid) {
            int sr = permR ? permR[gr] : gr;
            rr = resid + (size_t)sr * N;
        }
#pragma unroll
        for (int n = 0; n < TN; n++) {
            float vv = fmaxf(acc[m][n], 0.f);
            if (rr) vv += rr[col0 + n];
            C[(size_t)gr * N + col0 + n] = vv;
        }
    }
}

// ------------------------------ launch --------------------------------------
extern "C" void kernel_launch(void* const* d_in, const int* in_sizes, int n_in,
                              void* d_out, int out_size) {
    const float* support = (const float*)d_in[0];
    const float* query   = (const float*)d_in[1];
    const float* W1      = (const float*)d_in[2];   // [1024, 2048]
    const float* W2      = (const float*)d_in[3];   // [2048, 1024]
    float* out0 = (float*)d_out;
    float* out1 = out0 + (size_t)MROWS * DIM;

    norm_kernel<<<MROWS, 128>>>(support, query);
    cost_kernel<<<BATCH, 256>>>(support, query);
    lap_kernel<<<BATCH, 32>>>();

    // layer 1: h = relu(X @ W1^T)
    gemm_kernel<<<dim3(HID / 128, MROWS / 128), 256>>>(
        support, W1, nullptr, nullptr, 0, 1, 0, 0, HID, DIM);
    gemm_kernel<<<dim3(HID / 128, MROWS / 128), 256>>>(
        query, W1, nullptr, nullptr, 0, 2, 1, 0, HID, DIM);
    // layer 2: out = resid_perm + relu(h @ W2^T)
    gemm_kernel<<<dim3(DIM / 128, MROWS / 128), 256>>>(
        nullptr, W2, out0, support, 1, 0, 0, 0, DIM, HID);
    gemm_kernel<<<dim3(DIM / 128, MROWS / 128), 256>>>(
        nullptr, W2, out1, query, 2, 0, 0, 1, DIM, HID);
}

// round 6
// speedup vs baseline: 4.1151x; 4.1151x over previous
#include <cuda_runtime.h>
#include <math.h>
#include <stdint.h>

#define BATCH 32
#define NPTS  128
#define DIM   2048
#define HID   1024
#define MROWS (BATCH * NPTS)   // 4096
#define KC    32               // K floats per smem chunk (= 128B SW128 atom row)

// tcgen05 only exists in the sm_103a (arch-specific) compilation pass.
#ifdef __CUDA_ARCH_FEAT_SM103_ALL
#define HAS_TCGEN05 1
#endif

// ------------------------------ scratch ------------------------------------
__device__ float d_cost[BATCH * NPTS * NPTS];
__device__ float d_ns[MROWS];
__device__ float d_nq[MROWS];
__device__ int   d_perm[MROWS];
__device__ float d_h[2u * MROWS * HID];

// ------------------------------ PTX helpers ---------------------------------
__device__ __forceinline__ uint32_t smem_u32(const void* p) {
    uint32_t a;
    asm("{ .reg .u64 t; cvta.to.shared.u64 t, %1; cvt.u32.u64 %0, t; }"
        : "=r"(a) : "l"(p));
    return a;
}
#define SW128(o) ((o) ^ (((o) >> 3) & 0x70))

#ifdef HAS_TCGEN05
__device__ __forceinline__ float to_tf32(float x) {
    float r; asm("cvt.rna.tf32.f32 %0, %1;" : "=f"(r) : "f"(x)); return r;
}
#define TCGEN05_ALLOC(smem_addr, nCols) \
    asm volatile("tcgen05.alloc.cta_group::1.sync.aligned.shared::cta.b32 [%0], %1;" \
        :: "r"((uint32_t)(smem_addr)), "r"((uint32_t)(nCols)) : "memory")
#define TCGEN05_DEALLOC(tmem_addr, nCols) \
    asm volatile("tcgen05.dealloc.cta_group::1.sync.aligned.b32 %0, %1;" \
        :: "r"(tmem_addr), "r"((uint32_t)(nCols)))
#define TCGEN05_RELINQUISH() \
    asm volatile("tcgen05.relinquish_alloc_permit.cta_group::1.sync.aligned;")
#define TCGEN05_COMMIT(mbar) \
    asm volatile("tcgen05.commit.cta_group::1.mbarrier::arrive::one.shared::cluster.b64 [%0];" \
        :: "r"((uint32_t)(mbar)) : "memory")
#define TCGEN05_FENCE_AFTER() \
    asm volatile("tcgen05.fence::after_thread_sync;" ::: "memory")
#define TCGEN05_FENCE_BEFORE() \
    asm volatile("tcgen05.fence::before_thread_sync;" ::: "memory")
#define TCGEN05_WAIT_LD() \
    asm volatile("tcgen05.wait::ld.sync.aligned;" ::: "memory")
#define TCGEN05_LD_32X32B_X16(r, tmem_addr) \
    asm volatile("tcgen05.ld.sync.aligned.32x32b.x16.b32 " \
        "{%0, %1, %2, %3, %4, %5, %6, %7, %8, %9, %10, %11, %12, %13, %14, %15}, [%16];" \
        : "=r"((r)[0]), "=r"((r)[1]), "=r"((r)[2]), "=r"((r)[3]), \
          "=r"((r)[4]), "=r"((r)[5]), "=r"((r)[6]), "=r"((r)[7]), \
          "=r"((r)[8]), "=r"((r)[9]), "=r"((r)[10]), "=r"((r)[11]), \
          "=r"((r)[12]), "=r"((r)[13]), "=r"((r)[14]), "=r"((r)[15]) \
        : "r"(tmem_addr))
#define MBARRIER_INIT(mbar, count) \
    asm volatile("mbarrier.init.shared.b64 [%0], %1;" \
        :: "r"((uint32_t)(mbar)), "r"((uint32_t)(count)) : "memory")
#define MBARRIER_WAIT_PARITY(mbar, parity) do { \
    uint32_t _m = (uint32_t)(mbar); uint32_t _p = (uint32_t)(parity); uint32_t _d; \
    asm volatile("{\n\t.reg .pred p;\n\t" \
        "mbarrier.try_wait.parity.acquire.cta.shared::cta.b64 p, [%1], %2;\n\t" \
        "selp.b32 %0, 1, 0, p;\n\t}" : "=r"(_d) : "r"(_m), "r"(_p) : "memory"); \
    if (!_d) { \
        asm volatile("{\n\t.reg .pred P1;\n\t" \
            "WL_%=:\n\t" \
            "mbarrier.try_wait.parity.acquire.cta.shared::cta.b64 P1, [%0], %1, 0x989680;\n\t" \
            "@P1 bra.uni WD_%=;\n\t" \
            "bra.uni WL_%=;\n\t" \
            "WD_%=:\n\t}" :: "r"(_m), "r"(_p) : "memory"); \
    } \
} while (0)

// SS-mode tf32 MMA (cg1)
__device__ __forceinline__ void mma_tf32_ss(uint32_t d, uint64_t ad, uint64_t bd,
                                            uint32_t idesc, int acc) {
    asm volatile("{\n\t.reg .pred p;\n\t"
        "setp.ne.u32 p, %4, 0;\n\t"
        "tcgen05.mma.cta_group::1.kind::tf32 [%0], %1, %2, %3, {%5, %5, %5, %5}, p;\n\t"
        "}" :: "r"(d), "l"(ad), "l"(bd), "r"(idesc), "r"(acc), "r"(0u) : "memory");
}
// idesc: c=F32(1<<4), a=TF32(2<<7), b=TF32(2<<10), N=128(16<<17), M=128(8<<24)
#define IDESC_TF32 ((8u << 24) | (16u << 17) | (2u << 10) | (2u << 7) | (1u << 4))

__device__ __forceinline__ uint64_t make_desc_sw128(uint32_t addr) {
    return ((uint64_t)2 << 61) | ((uint64_t)1 << 46) | ((uint64_t)64 << 32)
         | ((uint64_t)1 << 16) | ((addr >> 4) & 0x3FFF);
}
#endif // HAS_TCGEN05

// ------------------------------ norms --------------------------------------
__global__ void norm_kernel(const float* __restrict__ S, const float* __restrict__ Q) {
    int r = blockIdx.x;
    int tid = threadIdx.x;
    const float* srow = S + (size_t)r * DIM;
    const float* qrow = Q + (size_t)r * DIM;
    float s = 0.f, q = 0.f;
    for (int k = tid; k < DIM; k += 128) {
        float a = srow[k]; s = fmaf(a, a, s);
        float c = qrow[k]; q = fmaf(c, c, q);
    }
    for (int off = 16; off; off >>= 1) {
        s += __shfl_down_sync(0xffffffffu, s, off);
        q += __shfl_down_sync(0xffffffffu, q, off);
    }
    __shared__ float ss[4], qq[4];
    if ((tid & 31) == 0) { ss[tid >> 5] = s; qq[tid >> 5] = q; }
    __syncthreads();
    if (tid == 0) {
        d_ns[r] = sqrtf(ss[0] + ss[1] + ss[2] + ss[3]);
        d_nq[r] = sqrtf(qq[0] + qq[1] + qq[2] + qq[3]);
    }
}

// ------------------------- cost (FFMA fp32, exact-ish) ----------------------
// grid (4, BATCH): 128x32 output tile per CTA, K=2048.  fp32 keeps the LAP
// input faithful to the reference (tf32 would risk permutation flips).
__global__ void __launch_bounds__(256) cost_kernel(const float* __restrict__ S,
                                                   const float* __restrict__ Q) {
    constexpr int BK = 16, BN = 32, TM = 4, TN = 4;
    __shared__ float As[BK][NPTS];
    __shared__ float Bs[BK][BN];
    int b = blockIdx.y, cb = blockIdx.x;          // column block (32 cols)
    const float* Sb = S + (size_t)b * NPTS * DIM;
    const float* Qb = Q + (size_t)b * NPTS * DIM + (size_t)cb * BN * DIM;
    int tid = threadIdx.x;
    int aRow0 = tid >> 2, aK0 = (tid & 3) << 2;   // rows aRow0, aRow0+64
    int aRow1 = aRow0 + 64;
    const float* Sr0 = Sb + (size_t)aRow0 * DIM + aK0;
    const float* Sr1 = Sb + (size_t)aRow1 * DIM + aK0;
    int bRow = tid >> 2;                           // 0..63, only <32 valid
    const float* Qr = Qb + (size_t)(bRow & 31) * DIM + aK0;
    int tx = tid & 7, ty = tid >> 3;               // 8 col-groups x 32 row-groups
    float acc[TM][TN];
#pragma unroll
    for (int m = 0; m < TM; m++)
#pragma unroll
        for (int n = 0; n < TN; n++) acc[m][n] = 0.f;

    for (int k0 = 0; k0 < DIM; k0 += BK) {
        float4 a0 = *(const float4*)(Sr0 + k0);
        float4 a1 = *(const float4*)(Sr1 + k0);
        float4 b0 = (bRow < 32) ? *(const float4*)(Qr + k0) : make_float4(0, 0, 0, 0);
        __syncthreads();
        As[aK0 + 0][aRow0] = a0.x; As[aK0 + 1][aRow0] = a0.y;
        As[aK0 + 2][aRow0] = a0.z; As[aK0 + 3][aRow0] = a0.w;
        As[aK0 + 0][aRow1] = a1.x; As[aK0 + 1][aRow1] = a1.y;
        As[aK0 + 2][aRow1] = a1.z; As[aK0 + 3][aRow1] = a1.w;
        if (bRow < 32) {
            Bs[aK0 + 0][bRow] = b0.x; Bs[aK0 + 1][bRow] = b0.y;
            Bs[aK0 + 2][bRow] = b0.z; Bs[aK0 + 3][bRow] = b0.w;
        }
        __syncthreads();
#pragma unroll
        for (int k = 0; k < BK; k++) {
            float a[TM], bb[TN];
#pragma unroll
            for (int m = 0; m < TM; m++) a[m] = As[k][ty * TM + m];
#pragma unroll
            for (int n = 0; n < TN; n++) bb[n] = Bs[k][tx * TN + n];
#pragma unroll
            for (int m = 0; m < TM; m++)
#pragma unroll
                for (int n = 0; n < TN; n++) acc[m][n] = fmaf(a[m], bb[n], acc[m][n]);
        }
    }
#pragma unroll
    for (int m = 0; m < TM; m++) {
        int r = ty * TM + m;
        float ni = d_ns[b * NPTS + r];
#pragma unroll
        for (int n = 0; n < TN; n++) {
            int c = cb * BN + tx * TN + n;
            float nj = d_nq[b * NPTS + c];
            d_cost[(size_t)b * NPTS * NPTS + r * NPTS + c] = 1.0f - acc[m][n] / (ni * nj);
        }
    }
}

// ------------------------- unified MLP GEMM ---------------------------------
// D[128,128 tile] = A[M,K] . B[N,K]^T.
// tcgen05 path (sm_103a cubin): SS tf32 MMA, K chunked by 32, smem
//   [0] tmem ptr, [8] mbar, [1024] A (16KB SW128), [17408] B (16KB SW128),
//   [33792] epilogue stage 128x17 f32.
// fallback path (generic PTX pass): FFMA 128x128x16 tile.
// mode: 0 = relu -> C ; 1 = relu + resid(permR row-gather) -> C
#define TG_SMEM 42496
__global__ void __launch_bounds__(256, 1)
tgemm_kernel(const float* __restrict__ Aext, const float* __restrict__ Bmat,
             float* __restrict__ Cext, const float* __restrict__ resid,
             int a_h, int c_h, int permA, int permR, int N, int K, int mode) {
    extern __shared__ char smem[];
    int tid = threadIdx.x;
    int bx = blockIdx.x, by = blockIdx.y;
    const float* A = a_h ? (d_h + (size_t)(a_h - 1) * MROWS * HID) : Aext;
    float* C = c_h ? (d_h + (size_t)(c_h - 1) * MROWS * HID) : Cext;

#ifdef HAS_TCGEN05
    float* St = (float*)(smem + 33792);
    uint32_t sb = smem_u32(smem);
    int wid = tid >> 5, lane = tid & 31;

    if (wid == 0) TCGEN05_ALLOC(sb, 128);
    if (tid == 0) MBARRIER_INIT(sb + 8, 1);
    __syncthreads();
    uint32_t tmem;
    asm volatile("ld.shared.b32 %0, [%1];" : "=r"(tmem) : "r"(sb));

    // per-thread load slots: idx -> (row = idx>>3, kgroup = idx&7), float4 each
    const float* ap[4]; const float* bp[4]; uint32_t soff[4];
#pragma unroll
    for (int i = 0; i < 4; i++) {
        int idx = tid + i * 256;
        int r = idx >> 3, kg = idx & 7;
        int gr = by * NPTS + r;
        int sr = permA ? d_perm[gr] : gr;
        ap[i] = A + (size_t)sr * K + kg * 4;
        bp[i] = Bmat + (size_t)(bx * NPTS + r) * K + kg * 4;
        soff[i] = SW128((uint32_t)(r * 128 + kg * 16));
    }
    uint64_t adesc = make_desc_sw128(sb + 1024);
    uint64_t bdesc = make_desc_sw128(sb + 17408);

    const int NCH = K / KC;
    for (int c = 0; c < NCH; c++) {
        float4 a4[4], b4[4];
#pragma unroll
        for (int i = 0; i < 4; i++) {
            a4[i] = *(const float4*)(ap[i] + c * KC);
            b4[i] = *(const float4*)(bp[i] + c * KC);
        }
        if (c) MBARRIER_WAIT_PARITY(sb + 8, (c - 1) & 1);   // prev MMA done with smem
#pragma unroll
        for (int i = 0; i < 4; i++) {
            float4 t;
            t.x = to_tf32(a4[i].x); t.y = to_tf32(a4[i].y);
            t.z = to_tf32(a4[i].z); t.w = to_tf32(a4[i].w);
            *(float4*)(smem + 1024 + soff[i]) = t;
            t.x = to_tf32(b4[i].x); t.y = to_tf32(b4[i].y);
            t.z = to_tf32(b4[i].z); t.w = to_tf32(b4[i].w);
            *(float4*)(smem + 17408 + soff[i]) = t;
        }
        __syncthreads();
        if (tid == 0) {
            asm volatile("fence.proxy.async.shared::cta;" ::: "memory");
#pragma unroll
            for (int k = 0; k < 4; k++)   // 4 x K=8 MMAs cover the 32-float chunk
                mma_tf32_ss(tmem, adesc + k * 2, bdesc + k * 2, IDESC_TF32, (c | k) != 0);
            TCGEN05_COMMIT(sb + 8);
        }
    }
    MBARRIER_WAIT_PARITY(sb + 8, (NCH - 1) & 1);
    TCGEN05_FENCE_AFTER();

    // ------------------ epilogue: 8 groups of 16 columns ------------------
    int wrow = tid >> 1, wc0 = (tid & 1) * 8;
    int wgr = by * NPTS + wrow;
    const float* rres = nullptr;
    if (mode == 1) {
        int sr = permR ? d_perm[wgr] : wgr;
        rres = resid + (size_t)sr * N;
    }
    for (int g = 0; g < 8; g++) {
        if (tid < 128) {                       // warps 0-3 own the 128 D lanes
            uint32_t r16[16];
            TCGEN05_LD_32X32B_X16(r16, tmem + g * 16);
            TCGEN05_WAIT_LD();
            int row = wid * 32 + lane;
#pragma unroll
            for (int cc = 0; cc < 16; cc++)
                St[row * 17 + cc] = __uint_as_float(r16[cc]);
        }
        __syncthreads();
        {
            int col = bx * NPTS + g * 16 + wc0;
            float o[8];
#pragma unroll
            for (int cc = 0; cc < 8; cc++) {
                float f = fmaxf(St[wrow * 17 + wc0 + cc], 0.f);
                if (mode == 1) f += rres[col + cc];
                o[cc] = f;
            }
            float* dst = C + (size_t)wgr * N + col;
            *(float4*)(dst)     = make_float4(o[0], o[1], o[2], o[3]);
            *(float4*)(dst + 4) = make_float4(o[4], o[5], o[6], o[7]);
        }
        __syncthreads();
    }
    TCGEN05_FENCE_BEFORE();
    if (wid == 0) { TCGEN05_RELINQUISH(); TCGEN05_DEALLOC(tmem, 128); }

#else  // ---------------- FFMA fallback (generic PTX pass) ------------------
    constexpr int BK = 16, TM = 8, TN = 8;
    float* As = (float*)smem;             // [BK][128]
    float* Bs = (float*)(smem + 8192);    // [BK][128]
    int aRow0 = tid >> 2, aK0 = (tid & 3) << 2;
    int aRow1 = aRow0 + 64;
    int g0 = by * NPTS + aRow0, g1 = by * NPTS + aRow1;
    int s0 = permA ? d_perm[g0] : g0;
    int s1 = permA ? d_perm[g1] : g1;
    const float* Xr0 = A + (size_t)s0 * K + aK0;
    const float* Xr1 = A + (size_t)s1 * K + aK0;
    const float* Wr0 = Bmat + (size_t)(bx * NPTS + aRow0) * K + aK0;
    const float* Wr1 = Bmat + (size_t)(bx * NPTS + aRow1) * K + aK0;
    int tx = tid & 15, ty = tid >> 4;
    float acc[TM][TN];
#pragma unroll
    for (int m = 0; m < TM; m++)
#pragma unroll
        for (int n = 0; n < TN; n++) acc[m][n] = 0.f;

    for (int k0 = 0; k0 < K; k0 += BK) {
        float4 a0 = *(const float4*)(Xr0 + k0);
        float4 a1 = *(const float4*)(Xr1 + k0);
        float4 b0 = *(const float4*)(Wr0 + k0);
        float4 b1 = *(const float4*)(Wr1 + k0);
        __syncthreads();
        As[(aK0 + 0) * 128 + aRow0] = a0.x; As[(aK0 + 1) * 128 + aRow0] = a0.y;
        As[(aK0 + 2) * 128 + aRow0] = a0.z; As[(aK0 + 3) * 128 + aRow0] = a0.w;
        As[(aK0 + 0) * 128 + aRow1] = a1.x; As[(aK0 + 1) * 128 + aRow1] = a1.y;
        As[(aK0 + 2) * 128 + aRow1] = a1.z; As[(aK0 + 3) * 128 + aRow1] = a1.w;
        Bs[(aK0 + 0) * 128 + aRow0] = b0.x; Bs[(aK0 + 1) * 128 + aRow0] = b0.y;
        Bs[(aK0 + 2) * 128 + aRow0] = b0.z; Bs[(aK0 + 3) * 128 + aRow0] = b0.w;
        Bs[(aK0 + 0) * 128 + aRow1] = b1.x; Bs[(aK0 + 1) * 128 + aRow1] = b1.y;
        Bs[(aK0 + 2) * 128 + aRow1] = b1.z; Bs[(aK0 + 3) * 128 + aRow1] = b1.w;
        __syncthreads();
#pragma unroll
        for (int k = 0; k < BK; k++) {
            float a[TM], bb[TN];
#pragma unroll
            for (int m = 0; m < TM; m++) a[m] = As[k * 128 + ty * TM + m];
#pragma unroll
            for (int n = 0; n < TN; n++) bb[n] = Bs[k * 128 + tx * TN + n];
#pragma unroll
            for (int m = 0; m < TM; m++)
#pragma unroll
                for (int n = 0; n < TN; n++) acc[m][n] = fmaf(a[m], bb[n], acc[m][n]);
        }
    }
    int row0 = by * NPTS + ty * TM, col0 = bx * NPTS + tx * TN;
#pragma unroll
    for (int m = 0; m < TM; m++) {
        int gr = row0 + m;
        const float* rr = nullptr;
        if (mode == 1) {
            int sr = permR ? d_perm[gr] : gr;
            rr = resid + (size_t)sr * N;
        }
#pragma unroll
        for (int n = 0; n < TN; n++) {
            float vv = fmaxf(acc[m][n], 0.f);
            if (rr) vv += rr[col0 + n];
            C[(size_t)gr * N + col0 + n] = vv;
        }
    }
#endif
}

// --------------------------- JV Hungarian (fast) ----------------------------
// fp32, cost matrix cached in shared, per-lane register column state,
// REDUX-based argmin with np.argmin first-min tie-break. One warp per batch.
__device__ __forceinline__ unsigned fkey(float f) {
    unsigned u = __float_as_uint(f);
    return (u & 0x80000000u) ? ~u : (u | 0x80000000u);
}
__device__ __forceinline__ float fuk(unsigned k) {
    k = (k & 0x80000000u) ? (k & 0x7fffffffu) : ~k;
    return __uint_as_float(k);
}

__global__ void lap_kernel() {
    extern __shared__ float csh[];                   // [128][128] cost, 64KB
    __shared__ float u_sh[NPTS + 1];
    __shared__ int   p_sh[NPTS + 1];
    __shared__ int   way_sh[NPTS + 1];
    int b = blockIdx.x;
    int lane = threadIdx.x;

    const float4* src = (const float4*)(d_cost + (size_t)b * NPTS * NPTS);
    float4* dst = (float4*)csh;
    for (int i = lane; i < NPTS * NPTS / 4; i += 32) dst[i] = src[i];
    for (int j = lane; j <= NPTS; j += 32) { u_sh[j] = 0.f; p_sh[j] = 0; way_sh[j] = 0; }
    __syncwarp();

    float v[4] = {0.f, 0.f, 0.f, 0.f};
    float minv[4];
    int used;                                         // 4-bit mask, cols 4*lane+1..+4

    for (int i = 1; i <= NPTS; i++) {
        if (lane == 0) p_sh[0] = i;
        minv[0] = minv[1] = minv[2] = minv[3] = INFINITY;
        used = 0;
        int j0 = 0;
        __syncwarp();
        while (true) {
            if (j0) {
                int ol = (j0 - 1) >> 2, ot = (j0 - 1) & 3;
                if (lane == ol) used |= 1 << ot;
            }
            int i0 = p_sh[j0];
            float ui0 = u_sh[i0];
            float4 c4 = *(const float4*)(csh + (i0 - 1) * NPTS + 4 * lane);
            float cc[4] = {c4.x, c4.y, c4.z, c4.w};
            float best = INFINITY; int jb = 0x7fffffff;
#pragma unroll
            for (int t = 0; t < 4; t++) {
                if (!((used >> t) & 1)) {
                    float cur = cc[t] - ui0 - v[t];
                    if (cur < minv[t]) { minv[t] = cur; way_sh[4 * lane + t + 1] = j0; }
                    if (minv[t] < best) { best = minv[t]; jb = 4 * lane + t + 1; }
                }
            }
            unsigned key = fkey(best);
            unsigned kmin = __reduce_min_sync(0xffffffffu, key);
            unsigned jc = (key == kmin) ? (unsigned)jb : 0xffffffffu;
            unsigned j1 = __reduce_min_sync(0xffffffffu, jc);
            float delta = fuk(kmin);
#pragma unroll
            for (int t = 0; t < 4; t++) {
                int j = 4 * lane + t + 1;
                if ((used >> t) & 1) {
                    v[t] -= delta;
                    u_sh[p_sh[j]] += delta;           // distinct rows: no conflict
                } else {
                    minv[t] -= delta;
                }
            }
            if (lane == 0) u_sh[p_sh[0]] += delta;    // column 0 (always "used")
            __syncwarp();
            j0 = (int)j1;
            if (p_sh[j0] == 0) break;
        }
        if (lane == 0) {                               // augment along way[]
            int jj = j0;
            while (jj) { int jn = way_sh[jj]; p_sh[jj] = p_sh[jn]; jj = jn; }
        }
        __syncwarp();
    }
    for (int j = lane + 1; j <= NPTS; j += 32)
        d_perm[b * NPTS + (p_sh[j] - 1)] = b * NPTS + (j - 1);
}

// ------------------------------ launch --------------------------------------
extern "C" void kernel_launch(void* const* d_in, const int* in_sizes, int n_in,
                              void* d_out, int out_size) {
    const float* support = (const float*)d_in[0];
    const float* query   = (const float*)d_in[1];
    const float* W1      = (const float*)d_in[2];   // [1024, 2048]
    const float* W2      = (const float*)d_in[3];   // [2048, 1024]
    float* out0 = (float*)d_out;
    float* out1 = out0 + (size_t)MROWS * DIM;

    cudaFuncSetAttribute(lap_kernel, cudaFuncAttributeMaxDynamicSharedMemorySize, 65536);
    cudaFuncSetAttribute(tgemm_kernel, cudaFuncAttributeMaxDynamicSharedMemorySize, TG_SMEM);

    norm_kernel<<<MROWS, 128>>>(support, query);
    cost_kernel<<<dim3(4, BATCH), 256>>>(support, query);
    lap_kernel<<<BATCH, 32, 65536>>>();

    // layer 1: h = relu(X @ W1^T)
    tgemm_kernel<<<dim3(HID / 128, MROWS / 128), 256, TG_SMEM>>>(
        support, W1, nullptr, nullptr, 0, 1, 0, 0, HID, DIM, 0);
    tgemm_kernel<<<dim3(HID / 128, MROWS / 128), 256, TG_SMEM>>>(
        query, W1, nullptr, nullptr, 0, 2, 1, 0, HID, DIM, 0);
    // layer 2: out = resid(perm) + relu(h @ W2^T)
    tgemm_kernel<<<dim3(DIM / 128, MROWS / 128), 256, TG_SMEM>>>(
        nullptr, W2, out0, support, 1, 0, 0, 0, DIM, HID, 1);
    tgemm_kernel<<<dim3(DIM / 128, MROWS / 128), 256, TG_SMEM>>>(
        nullptr, W2, out1, query, 2, 0, 0, 1, DIM, HID, 1);
}

// round 7
// speedup vs baseline: 6.0012x; 1.4583x over previous
#include <cuda_runtime.h>
#include <math.h>
#include <stdint.h>

#define BATCH 32
#define NPTS  128
#define DIM   2048
#define HID   1024
#define MROWS (BATCH * NPTS)   // 4096
#define KC    32               // K floats per smem chunk (= 128B SW128 atom row)
#define FULLM 0xffffffffu

// tcgen05 / f32x2 only exist in the sm_103a (arch-specific) compilation pass.
#ifdef __CUDA_ARCH_FEAT_SM103_ALL
#define HAS_TCGEN05 1
#endif

// ------------------------------ scratch ------------------------------------
__device__ float d_cost[BATCH * NPTS * NPTS];
__device__ float d_ns[MROWS];
__device__ float d_nq[MROWS];
__device__ int   d_perm[MROWS];                 // d_perm[g] = global src row of out1 row g
__device__ float d_h[2u * MROWS * HID];         // hidden activations
__device__ float d_tmp[(size_t)MROWS * DIM];    // query + mlp(query), unpermuted

// ------------------------------ PTX helpers ---------------------------------
__device__ __forceinline__ uint32_t smem_u32(const void* p) {
    uint32_t a;
    asm("{ .reg .u64 t; cvta.to.shared.u64 t, %1; cvt.u32.u64 %0, t; }"
        : "=r"(a) : "l"(p));
    return a;
}
#define SW128(o) ((o) ^ (((o) >> 3) & 0x70))

#ifdef HAS_TCGEN05
__device__ __forceinline__ float to_tf32(float x) {
    float r; asm("cvt.rna.tf32.f32 %0, %1;" : "=f"(r) : "f"(x)); return r;
}
#define TCGEN05_ALLOC(smem_addr, nCols) \
    asm volatile("tcgen05.alloc.cta_group::1.sync.aligned.shared::cta.b32 [%0], %1;" \
        :: "r"((uint32_t)(smem_addr)), "r"((uint32_t)(nCols)) : "memory")
#define TCGEN05_DEALLOC(tmem_addr, nCols) \
    asm volatile("tcgen05.dealloc.cta_group::1.sync.aligned.b32 %0, %1;" \
        :: "r"(tmem_addr), "r"((uint32_t)(nCols)))
#define TCGEN05_RELINQUISH() \
    asm volatile("tcgen05.relinquish_alloc_permit.cta_group::1.sync.aligned;")
#define TCGEN05_COMMIT(mbar) \
    asm volatile("tcgen05.commit.cta_group::1.mbarrier::arrive::one.shared::cluster.b64 [%0];" \
        :: "r"((uint32_t)(mbar)) : "memory")
#define TCGEN05_FENCE_AFTER() \
    asm volatile("tcgen05.fence::after_thread_sync;" ::: "memory")
#define TCGEN05_FENCE_BEFORE() \
    asm volatile("tcgen05.fence::before_thread_sync;" ::: "memory")
#define TCGEN05_WAIT_LD() \
    asm volatile("tcgen05.wait::ld.sync.aligned;" ::: "memory")
#define TCGEN05_LD_32X32B_X16(r, tmem_addr) \
    asm volatile("tcgen05.ld.sync.aligned.32x32b.x16.b32 " \
        "{%0, %1, %2, %3, %4, %5, %6, %7, %8, %9, %10, %11, %12, %13, %14, %15}, [%16];" \
        : "=r"((r)[0]), "=r"((r)[1]), "=r"((r)[2]), "=r"((r)[3]), \
          "=r"((r)[4]), "=r"((r)[5]), "=r"((r)[6]), "=r"((r)[7]), \
          "=r"((r)[8]), "=r"((r)[9]), "=r"((r)[10]), "=r"((r)[11]), \
          "=r"((r)[12]), "=r"((r)[13]), "=r"((r)[14]), "=r"((r)[15]) \
        : "r"(tmem_addr))
#define MBARRIER_INIT(mbar, count) \
    asm volatile("mbarrier.init.shared.b64 [%0], %1;" \
        :: "r"((uint32_t)(mbar)), "r"((uint32_t)(count)) : "memory")
#define MBARRIER_WAIT_PARITY(mbar, parity) do { \
    uint32_t _m = (uint32_t)(mbar); uint32_t _p = (uint32_t)(parity); uint32_t _d; \
    asm volatile("{\n\t.reg .pred p;\n\t" \
        "mbarrier.try_wait.parity.acquire.cta.shared::cta.b64 p, [%1], %2;\n\t" \
        "selp.b32 %0, 1, 0, p;\n\t}" : "=r"(_d) : "r"(_m), "r"(_p) : "memory"); \
    if (!_d) { \
        asm volatile("{\n\t.reg .pred P1;\n\t" \
            "WL_%=:\n\t" \
            "mbarrier.try_wait.parity.acquire.cta.shared::cta.b64 P1, [%0], %1, 0x989680;\n\t" \
            "@P1 bra.uni WD_%=;\n\t" \
            "bra.uni WL_%=;\n\t" \
            "WD_%=:\n\t}" :: "r"(_m), "r"(_p) : "memory"); \
    } \
} while (0)

__device__ __forceinline__ void mma_tf32_ss(uint32_t d, uint64_t ad, uint64_t bd,
                                            uint32_t idesc, int acc) {
    asm volatile("{\n\t.reg .pred p;\n\t"
        "setp.ne.u32 p, %4, 0;\n\t"
        "tcgen05.mma.cta_group::1.kind::tf32 [%0], %1, %2, %3, {%5, %5, %5, %5}, p;\n\t"
        "}" :: "r"(d), "l"(ad), "l"(bd), "r"(idesc), "r"(acc), "r"(0u) : "memory");
}
// idesc: c=F32(1<<4), a=TF32(2<<7), b=TF32(2<<10), N=128(16<<17), M=128(8<<24)
#define IDESC_TF32 ((8u << 24) | (16u << 17) | (2u << 10) | (2u << 7) | (1u << 4))

__device__ __forceinline__ uint64_t make_desc_sw128(uint32_t addr) {
    return ((uint64_t)2 << 61) | ((uint64_t)1 << 46) | ((uint64_t)64 << 32)
         | ((uint64_t)1 << 16) | ((addr >> 4) & 0x3FFF);
}

__device__ __forceinline__ void fma2(unsigned long long& d,
                                     unsigned long long a, unsigned long long b) {
    asm("fma.rn.f32x2 %0, %1, %2, %0;" : "+l"(d) : "l"(a), "l"(b));
}
#endif // HAS_TCGEN05

// ------------------------------ norms --------------------------------------
__global__ void norm_kernel(const float* __restrict__ S, const float* __restrict__ Q) {
    int r = blockIdx.x;
    int tid = threadIdx.x;
    const float* srow = S + (size_t)r * DIM;
    const float* qrow = Q + (size_t)r * DIM;
    float s = 0.f, q = 0.f;
    for (int k = tid; k < DIM; k += 128) {
        float a = srow[k]; s = fmaf(a, a, s);
        float c = qrow[k]; q = fmaf(c, c, q);
    }
    for (int off = 16; off; off >>= 1) {
        s += __shfl_down_sync(FULLM, s, off);
        q += __shfl_down_sync(FULLM, q, off);
    }
    __shared__ float ss[4], qq[4];
    if ((tid & 31) == 0) { ss[tid >> 5] = s; qq[tid >> 5] = q; }
    __syncthreads();
    if (tid == 0) {
        d_ns[r] = sqrtf(ss[0] + ss[1] + ss[2] + ss[3]);
        d_nq[r] = sqrtf(qq[0] + qq[1] + qq[2] + qq[3]);
    }
}

// ------------------------- cost (fp32, f32x2 packed) ------------------------
// grid (4, BATCH): 128x32 output tile per CTA, K=2048. fp32-class accuracy so
// the LAP input stays faithful (tf32 would risk permutation flips).
__global__ void __launch_bounds__(256) cost_kernel(const float* __restrict__ S,
                                                   const float* __restrict__ Q) {
    constexpr int BN = 32, TM = 4, TN = 4;
    __shared__ float2 As2[8][NPTS];   // [kk][row], kk = k-pair within 16-block
    __shared__ float2 Bs2[8][BN];
    int b = blockIdx.y, cb = blockIdx.x;
    const float* Sb = S + (size_t)b * NPTS * DIM;
    const float* Qb = Q + (size_t)b * NPTS * DIM + (size_t)cb * BN * DIM;
    int tid = threadIdx.x;
    int aRow0 = tid >> 2, aK0 = (tid & 3) << 2;
    int aRow1 = aRow0 + 64;
    const float* Sr0 = Sb + (size_t)aRow0 * DIM + aK0;
    const float* Sr1 = Sb + (size_t)aRow1 * DIM + aK0;
    int bRow = tid >> 2;
    const float* Qr = Qb + (size_t)(bRow & 31) * DIM + aK0;
    int tx = tid & 7, ty = tid >> 3;
    int kk0 = aK0 >> 1;

#ifdef HAS_TCGEN05
    unsigned long long acc2[TM][TN];
#pragma unroll
    for (int m = 0; m < TM; m++)
#pragma unroll
        for (int n = 0; n < TN; n++) acc2[m][n] = 0ull;

    for (int k0 = 0; k0 < DIM; k0 += 16) {
        float4 a0 = *(const float4*)(Sr0 + k0);
        float4 a1 = *(const float4*)(Sr1 + k0);
        float4 b0 = (bRow < 32) ? *(const float4*)(Qr + k0) : make_float4(0, 0, 0, 0);
        __syncthreads();
        As2[kk0][aRow0] = make_float2(a0.x, a0.y);
        As2[kk0 + 1][aRow0] = make_float2(a0.z, a0.w);
        As2[kk0][aRow1] = make_float2(a1.x, a1.y);
        As2[kk0 + 1][aRow1] = make_float2(a1.z, a1.w);
        if (bRow < 32) {
            Bs2[kk0][bRow] = make_float2(b0.x, b0.y);
            Bs2[kk0 + 1][bRow] = make_float2(b0.z, b0.w);
        }
        __syncthreads();
#pragma unroll
        for (int kk = 0; kk < 8; kk++) {
            unsigned long long a2[TM], b2[TN];
#pragma unroll
            for (int m = 0; m < TM; m++)
                a2[m] = *(const unsigned long long*)&As2[kk][ty * TM + m];
#pragma unroll
            for (int n = 0; n < TN; n++)
                b2[n] = *(const unsigned long long*)&Bs2[kk][tx * TN + n];
#pragma unroll
            for (int m = 0; m < TM; m++)
#pragma unroll
                for (int n = 0; n < TN; n++) fma2(acc2[m][n], a2[m], b2[n]);
        }
    }
#pragma unroll
    for (int m = 0; m < TM; m++) {
        int r = ty * TM + m;
        float ni = d_ns[b * NPTS + r];
#pragma unroll
        for (int n = 0; n < TN; n++) {
            int c = cb * BN + tx * TN + n;
            float nj = d_nq[b * NPTS + c];
            float lo = __uint_as_float((unsigned)(acc2[m][n] & 0xffffffffull));
            float hi = __uint_as_float((unsigned)(acc2[m][n] >> 32));
            d_cost[(size_t)b * NPTS * NPTS + r * NPTS + c] = 1.0f - (lo + hi) / (ni * nj);
        }
    }
#else
    float acc[TM][TN];
#pragma unroll
    for (int m = 0; m < TM; m++)
#pragma unroll
        for (int n = 0; n < TN; n++) acc[m][n] = 0.f;
    for (int k0 = 0; k0 < DIM; k0 += 16) {
        float4 a0 = *(const float4*)(Sr0 + k0);
        float4 a1 = *(const float4*)(Sr1 + k0);
        float4 b0 = (bRow < 32) ? *(const float4*)(Qr + k0) : make_float4(0, 0, 0, 0);
        __syncthreads();
        As2[kk0][aRow0] = make_float2(a0.x, a0.y);
        As2[kk0 + 1][aRow0] = make_float2(a0.z, a0.w);
        As2[kk0][aRow1] = make_float2(a1.x, a1.y);
        As2[kk0 + 1][aRow1] = make_float2(a1.z, a1.w);
        if (bRow < 32) {
            Bs2[kk0][bRow] = make_float2(b0.x, b0.y);
            Bs2[kk0 + 1][bRow] = make_float2(b0.z, b0.w);
        }
        __syncthreads();
#pragma unroll
        for (int kk = 0; kk < 8; kk++) {
#pragma unroll
            for (int m = 0; m < TM; m++) {
                float2 a = As2[kk][ty * TM + m];
#pragma unroll
                for (int n = 0; n < TN; n++) {
                    float2 bb = Bs2[kk][tx * TN + n];
                    acc[m][n] = fmaf(a.x, bb.x, acc[m][n]);
                    acc[m][n] = fmaf(a.y, bb.y, acc[m][n]);
                }
            }
        }
    }
#pragma unroll
    for (int m = 0; m < TM; m++) {
        int r = ty * TM + m;
        float ni = d_ns[b * NPTS + r];
#pragma unroll
        for (int n = 0; n < TN; n++) {
            int c = cb * BN + tx * TN + n;
            float nj = d_nq[b * NPTS + c];
            d_cost[(size_t)b * NPTS * NPTS + r * NPTS + c] = 1.0f - acc[m][n] / (ni * nj);
        }
    }
#endif
}

// ------------------------- MLP GEMM (double-buffered) -----------------------
// tcgen05 path: SS tf32 MMA, K chunked by 32, 2 smem stages.
// smem: [0] tmem ptr, [8] mbar0, [16] mbar1,
//       [1024 + s*32768] stage s: A 16KB, B 16KB  (SW128)
//       [66560] epilogue stage 128x17 f32 (8704B)
// mode: 0 = relu -> C ; 1 = relu + resid -> C   (no permutation anywhere)
#define TG_SMEM 75264
__global__ void __launch_bounds__(256, 1)
tgemm_kernel(const float* __restrict__ Aext, const float* __restrict__ Bmat,
             float* __restrict__ Cext, const float* __restrict__ resid,
             int a_h, int c_h, int N, int K, int mode) {
    extern __shared__ char smem[];
    int tid = threadIdx.x;
    int bx = blockIdx.x, by = blockIdx.y;
    const float* A = a_h ? (d_h + (size_t)(a_h - 1) * MROWS * HID) : Aext;
    float* C = (c_h == 0) ? Cext
             : (c_h == 3) ? d_tmp
             : (d_h + (size_t)(c_h - 1) * MROWS * HID);

#ifdef HAS_TCGEN05
    float* St = (float*)(smem + 66560);
    uint32_t sb = smem_u32(smem);
    int wid = tid >> 5, lane = tid & 31;

    if (wid == 0) TCGEN05_ALLOC(sb, 128);
    if (tid == 0) { MBARRIER_INIT(sb + 8, 1); MBARRIER_INIT(sb + 16, 1); }
    __syncthreads();
    uint32_t tmem;
    asm volatile("ld.shared.b32 %0, [%1];" : "=r"(tmem) : "r"(sb));

    const float* ap[4]; const float* bp[4]; uint32_t soff[4];
#pragma unroll
    for (int i = 0; i < 4; i++) {
        int idx = tid + i * 256;
        int r = idx >> 3, kg = idx & 7;
        ap[i] = A + (size_t)(by * NPTS + r) * K + kg * 4;
        bp[i] = Bmat + (size_t)(bx * NPTS + r) * K + kg * 4;
        soff[i] = SW128((uint32_t)(r * 128 + kg * 16));
    }
    uint64_t adesc[2] = { make_desc_sw128(sb + 1024), make_desc_sw128(sb + 1024 + 32768) };
    uint64_t bdesc[2] = { make_desc_sw128(sb + 17408), make_desc_sw128(sb + 17408 + 32768) };

    const int NCH = K / KC;
    for (int c = 0; c < NCH; c++) {
        int s = c & 1;
        uint32_t abase = 1024 + (uint32_t)s * 32768;
        float4 a4[4], b4[4];
#pragma unroll
        for (int i = 0; i < 4; i++) {
            a4[i] = *(const float4*)(ap[i] + c * KC);
            b4[i] = *(const float4*)(bp[i] + c * KC);
        }
        if (c >= 2) MBARRIER_WAIT_PARITY(sb + 8 + 8 * s, ((c >> 1) - 1) & 1);
#pragma unroll
        for (int i = 0; i < 4; i++) {
            float4 t;
            t.x = to_tf32(a4[i].x); t.y = to_tf32(a4[i].y);
            t.z = to_tf32(a4[i].z); t.w = to_tf32(a4[i].w);
            *(float4*)(smem + abase + soff[i]) = t;
            t.x = to_tf32(b4[i].x); t.y = to_tf32(b4[i].y);
            t.z = to_tf32(b4[i].z); t.w = to_tf32(b4[i].w);
            *(float4*)(smem + abase + 16384 + soff[i]) = t;
        }
        __syncthreads();
        if (tid == 0) {
            asm volatile("fence.proxy.async.shared::cta;" ::: "memory");
#pragma unroll
            for (int k = 0; k < 4; k++)
                mma_tf32_ss(tmem, adesc[s] + k * 2, bdesc[s] + k * 2, IDESC_TF32, (c | k) != 0);
            TCGEN05_COMMIT(sb + 8 + 8 * s);
        }
    }
    {   // final commit covers all prior MMAs from the issuing thread
        int s_last = (NCH - 1) & 1;
        MBARRIER_WAIT_PARITY(sb + 8 + 8 * s_last, ((NCH - 1) >> 1) & 1);
    }
    TCGEN05_FENCE_AFTER();

    // ------------------ epilogue: 8 groups of 16 columns ------------------
    int wrow = tid >> 1, wc0 = (tid & 1) * 8;
    int wgr = by * NPTS + wrow;
    const float* rres = (mode == 1) ? (resid + (size_t)wgr * N) : nullptr;
    for (int g = 0; g < 8; g++) {
        if (tid < 128) {
            uint32_t r16[16];
            TCGEN05_LD_32X32B_X16(r16, tmem + g * 16);
            TCGEN05_WAIT_LD();
            int row = wid * 32 + lane;
#pragma unroll
            for (int cc = 0; cc < 16; cc++)
                St[row * 17 + cc] = __uint_as_float(r16[cc]);
        }
        __syncthreads();
        {
            int col = bx * NPTS + g * 16 + wc0;
            float o[8];
#pragma unroll
            for (int cc = 0; cc < 8; cc++) {
                float f = fmaxf(St[wrow * 17 + wc0 + cc], 0.f);
                if (mode == 1) f += rres[col + cc];
                o[cc] = f;
            }
            float* dst = C + (size_t)wgr * N + col;
            *(float4*)(dst)     = make_float4(o[0], o[1], o[2], o[3]);
            *(float4*)(dst + 4) = make_float4(o[4], o[5], o[6], o[7]);
        }
        __syncthreads();
    }
    TCGEN05_FENCE_BEFORE();
    if (wid == 0) { TCGEN05_RELINQUISH(); TCGEN05_DEALLOC(tmem, 128); }

#else  // ---------------- FFMA fallback (generic PTX pass) ------------------
    constexpr int BK = 16, TM = 8, TN = 8;
    float* As = (float*)smem;
    float* Bs = (float*)(smem + 8192);
    int aRow0 = tid >> 2, aK0 = (tid & 3) << 2;
    int aRow1 = aRow0 + 64;
    const float* Xr0 = A + (size_t)(by * NPTS + aRow0) * K + aK0;
    const float* Xr1 = A + (size_t)(by * NPTS + aRow1) * K + aK0;
    const float* Wr0 = Bmat + (size_t)(bx * NPTS + aRow0) * K + aK0;
    const float* Wr1 = Bmat + (size_t)(bx * NPTS + aRow1) * K + aK0;
    int tx = tid & 15, ty = tid >> 4;
    float acc[TM][TN];
#pragma unroll
    for (int m = 0; m < TM; m++)
#pragma unroll
        for (int n = 0; n < TN; n++) acc[m][n] = 0.f;
    for (int k0 = 0; k0 < K; k0 += BK) {
        float4 a0 = *(const float4*)(Xr0 + k0);
        float4 a1 = *(const float4*)(Xr1 + k0);
        float4 b0 = *(const float4*)(Wr0 + k0);
        float4 b1 = *(const float4*)(Wr1 + k0);
        __syncthreads();
        As[(aK0 + 0) * 128 + aRow0] = a0.x; As[(aK0 + 1) * 128 + aRow0] = a0.y;
        As[(aK0 + 2) * 128 + aRow0] = a0.z; As[(aK0 + 3) * 128 + aRow0] = a0.w;
        As[(aK0 + 0) * 128 + aRow1] = a1.x; As[(aK0 + 1) * 128 + aRow1] = a1.y;
        As[(aK0 + 2) * 128 + aRow1] = a1.z; As[(aK0 + 3) * 128 + aRow1] = a1.w;
        Bs[(aK0 + 0) * 128 + aRow0] = b0.x; Bs[(aK0 + 1) * 128 + aRow0] = b0.y;
        Bs[(aK0 + 2) * 128 + aRow0] = b0.z; Bs[(aK0 + 3) * 128 + aRow0] = b0.w;
        Bs[(aK0 + 0) * 128 + aRow1] = b1.x; Bs[(aK0 + 1) * 128 + aRow1] = b1.y;
        Bs[(aK0 + 2) * 128 + aRow1] = b1.z; Bs[(aK0 + 3) * 128 + aRow1] = b1.w;
        __syncthreads();
#pragma unroll
        for (int k = 0; k < BK; k++) {
#pragma unroll
            for (int m = 0; m < TM; m++) {
                float a = As[k * 128 + ty * TM + m];
#pragma unroll
                for (int n = 0; n < TN; n++)
                    acc[m][n] = fmaf(a, Bs[k * 128 + tx * TN + n], acc[m][n]);
            }
        }
    }
    int row0 = by * NPTS + ty * TM, col0 = bx * NPTS + tx * TN;
#pragma unroll
    for (int m = 0; m < TM; m++) {
        int gr = row0 + m;
        const float* rr = (mode == 1) ? (resid + (size_t)gr * N) : nullptr;
#pragma unroll
        for (int n = 0; n < TN; n++) {
            float vv = fmaxf(acc[m][n], 0.f);
            if (rr) vv += rr[col0 + n];
            C[(size_t)gr * N + col0 + n] = vv;
        }
    }
#endif
}

// --------------------------- JV Hungarian (fast) ----------------------------
// fp32, cost cached in shared. Column-reduction + greedy init (feasible duals,
// CS-consistent partial matching), then absolute-distance Dijkstra
// augmentation with deferred dual updates. One warp per batch.
__device__ __forceinline__ unsigned fkey(float f) {
    unsigned u = __float_as_uint(f);
    return (u & 0x80000000u) ? ~u : (u | 0x80000000u);
}
__device__ __forceinline__ float fuk(unsigned k) {
    k = (k & 0x80000000u) ? (k & 0x7fffffffu) : ~k;
    return __uint_as_float(k);
}

__global__ void lap_kernel() {
    extern __shared__ float csh[];            // [128][128] cost, 64KB
    __shared__ float u_sh[NPTS];              // row potentials
    __shared__ int   roc_sh[NPTS];            // row_of_col
    __shared__ int   cor_sh[NPTS];            // col_of_row (-1 = unmatched)
    __shared__ int   way_sh[NPTS];            // predecessor column
    __shared__ int   im_sh[NPTS];             // argmin row per column (init)
    int b = blockIdx.x, lane = threadIdx.x;

    const float4* src = (const float4*)(d_cost + (size_t)b * NPTS * NPTS);
    float4* dst = (float4*)csh;
    for (int i = lane; i < NPTS * NPTS / 4; i += 32) dst[i] = src[i];
    for (int r = lane; r < NPTS; r += 32) { u_sh[r] = 0.f; cor_sh[r] = -1; }
    __syncwarp();

    // column reduction: lane owns columns 4*lane .. 4*lane+3
    float v[4] = {INFINITY, INFINITY, INFINITY, INFINITY};
    int im[4] = {0, 0, 0, 0};
    for (int i = 0; i < NPTS; i++) {
        float4 c4 = *(const float4*)(csh + i * NPTS + 4 * lane);
        float cc[4] = {c4.x, c4.y, c4.z, c4.w};
#pragma unroll
        for (int t = 0; t < 4; t++)
            if (cc[t] < v[t]) { v[t] = cc[t]; im[t] = i; }
    }
#pragma unroll
    for (int t = 0; t < 4; t++) im_sh[4 * lane + t] = im[t];
    __syncwarp();
    if (lane == 0) {
        for (int j = 0; j < NPTS; j++) {
            int i = im_sh[j];
            if (cor_sh[i] < 0) { cor_sh[i] = j; roc_sh[j] = i; }
            else roc_sh[j] = -1;
        }
    }
    __syncwarp();

    // augment each unmatched row
    for (int i = 0; i < NPTS; i++) {
        if (cor_sh[i] >= 0) continue;          // uniform (shared read)
        float dist[4] = {INFINITY, INFINITY, INFINITY, INFINITY};
        int usedm = 0;
        int i0 = i, j0 = -1, jfin = -1;
        float D = 0.f, ui0 = u_sh[i0];
        for (int it = 0; it < NPTS + 2; it++) {
            float4 c4 = *(const float4*)(csh + i0 * NPTS + 4 * lane);
            float cc[4] = {c4.x, c4.y, c4.z, c4.w};
            float best = INFINITY; int jb = 0x7fffffff;
#pragma unroll
            for (int t = 0; t < 4; t++) {
                if (!((usedm >> t) & 1)) {
                    float nd = D + cc[t] - ui0 - v[t];
                    if (nd < dist[t]) { dist[t] = nd; way_sh[4 * lane + t] = j0; }
                    if (dist[t] < best) { best = dist[t]; jb = 4 * lane + t; }
                }
            }
            unsigned key = fkey(best);
            unsigned kmin = __reduce_min_sync(FULLM, key);
            unsigned bal = __ballot_sync(FULLM, key == kmin);
            int srcl = __ffs(bal) - 1;
            int j1 = __shfl_sync(FULLM, jb, srcl);
            D = fuk(kmin);
            int i1 = roc_sh[j1];
            if (i1 < 0) { jfin = j1; break; }
            { int ol = j1 >> 2, ot = j1 & 3; if (lane == ol) usedm |= 1 << ot; }
            i0 = i1; ui0 = u_sh[i0]; j0 = j1;
        }
        __syncwarp();
        // deferred dual updates: used j: v[j] -= D - dist[j]; u[roc[j]] += same
#pragma unroll
        for (int t = 0; t < 4; t++) {
            if ((usedm >> t) & 1) {
                int j = 4 * lane + t;
                float dd = D - dist[t];
                v[t] -= dd;
                u_sh[roc_sh[j]] += dd;         // distinct rows: no conflict
            }
        }
        if (lane == 0) u_sh[i] += D;
        __syncwarp();
        if (lane == 0) {                       // augment along way[]
            int j = jfin;
            while (way_sh[j] >= 0) { int jp = way_sh[j]; roc_sh[j] = roc_sh[jp]; j = jp; }
            roc_sh[j] = i;
        }
        __syncwarp();
    }
    for (int j = lane; j < NPTS; j += 32)
        d_perm[b * NPTS + roc_sh[j]] = b * NPTS + j;
}

// --------------------------- out1 permutation gather ------------------------
__global__ void gather_kernel(float* __restrict__ out1) {
    int g = blockIdx.x;
    int src = d_perm[g];
    const float4* s = (const float4*)(d_tmp + (size_t)src * DIM);
    float4* d = (float4*)(out1 + (size_t)g * DIM);
    for (int k = threadIdx.x; k < DIM / 4; k += 256) d[k] = s[k];
}

// ------------------------------ launch --------------------------------------
static cudaStream_t g_s2 = nullptr;
static cudaEvent_t g_evF = nullptr, g_evJ = nullptr;

extern "C" void kernel_launch(void* const* d_in, const int* in_sizes, int n_in,
                              void* d_out, int out_size) {
    const float* support = (const float*)d_in[0];
    const float* query   = (const float*)d_in[1];
    const float* W1      = (const float*)d_in[2];   // [1024, 2048]
    const float* W2      = (const float*)d_in[3];   // [2048, 1024]
    float* out0 = (float*)d_out;
    float* out1 = out0 + (size_t)MROWS * DIM;

    if (!g_s2) {   // one-time resource creation (first call is uncaptured)
        cudaStreamCreateWithFlags(&g_s2, cudaStreamNonBlocking);
        cudaEventCreateWithFlags(&g_evF, cudaEventDisableTiming);
        cudaEventCreateWithFlags(&g_evJ, cudaEventDisableTiming);
        cudaFuncSetAttribute(lap_kernel, cudaFuncAttributeMaxDynamicSharedMemorySize, 65536);
        cudaFuncSetAttribute(tgemm_kernel, cudaFuncAttributeMaxDynamicSharedMemorySize, TG_SMEM);
    }

    // fork: GEMM chain (independent of matching) runs on s2 concurrently
    cudaEventRecord(g_evF, 0);
    cudaStreamWaitEvent(g_s2, g_evF, 0);

    // stream 0: matching path
    norm_kernel<<<MROWS, 128>>>(support, query);
    cost_kernel<<<dim3(4, BATCH), 256>>>(support, query);
    lap_kernel<<<BATCH, 32, 65536>>>();

    // stream s2: MLP (no permutation; perm commutes with row-wise MLP)
    tgemm_kernel<<<dim3(HID / 128, MROWS / 128), 256, TG_SMEM, g_s2>>>(
        support, W1, nullptr, nullptr, 0, 1, HID, DIM, 0);
    tgemm_kernel<<<dim3(HID / 128, MROWS / 128), 256, TG_SMEM, g_s2>>>(
        query, W1, nullptr, nullptr, 0, 2, HID, DIM, 0);
    tgemm_kernel<<<dim3(DIM / 128, MROWS / 128), 256, TG_SMEM, g_s2>>>(
        nullptr, W2, out0, support, 1, 0, DIM, HID, 1);
    tgemm_kernel<<<dim3(DIM / 128, MROWS / 128), 256, TG_SMEM, g_s2>>>(
        nullptr, W2, nullptr, query, 2, 3, DIM, HID, 1);   // -> d_tmp

    // join, then permute out1
    cudaEventRecord(g_evJ, g_s2);
    cudaStreamWaitEvent(0, g_evJ, 0);
    gather_kernel<<<MROWS, 256>>>(out1);
}

// round 9
// speedup vs baseline: 6.7448x; 1.1239x over previous
#include <cuda_runtime.h>
#include <math.h>
#include <stdint.h>

#define BATCH 32
#define NPTS  128
#define DIM   2048
#define HID   1024
#define MROWS (BATCH * NPTS)   // 4096
#define KC    32               // K floats per smem chunk (= 128B SW128 atom row)
#define FULLM 0xffffffffu

// tcgen05 / f32x2 only exist in the sm_103a (arch-specific) compilation pass.
#ifdef __CUDA_ARCH_FEAT_SM103_ALL
#define HAS_TCGEN05 1
#endif

// ------------------------------ scratch ------------------------------------
__device__ float d_cost[BATCH * NPTS * NPTS];
__device__ float d_ns[MROWS];
__device__ float d_nq[MROWS];
__device__ int   d_perm[MROWS];                 // d_perm[g] = global src row of out1 row g
__device__ float d_h[2u * MROWS * HID];         // hidden acts: rows 0..4095 support, 4096..8191 query
__device__ float d_tmp[(size_t)MROWS * DIM];    // query + mlp(query), unpermuted

// ------------------------------ PTX helpers ---------------------------------
__device__ __forceinline__ uint32_t smem_u32(const void* p) {
    uint32_t a;
    asm("{ .reg .u64 t; cvta.to.shared.u64 t, %1; cvt.u32.u64 %0, t; }"
        : "=r"(a) : "l"(p));
    return a;
}
#define SW128(o) ((o) ^ (((o) >> 3) & 0x70))

#ifdef HAS_TCGEN05
__device__ __forceinline__ float to_tf32(float x) {
    float r; asm("cvt.rna.tf32.f32 %0, %1;" : "=f"(r) : "f"(x)); return r;
}
#define TCGEN05_ALLOC(smem_addr, nCols) \
    asm volatile("tcgen05.alloc.cta_group::1.sync.aligned.shared::cta.b32 [%0], %1;" \
        :: "r"((uint32_t)(smem_addr)), "r"((uint32_t)(nCols)) : "memory")
#define TCGEN05_DEALLOC(tmem_addr, nCols) \
    asm volatile("tcgen05.dealloc.cta_group::1.sync.aligned.b32 %0, %1;" \
        :: "r"(tmem_addr), "r"((uint32_t)(nCols)))
#define TCGEN05_RELINQUISH() \
    asm volatile("tcgen05.relinquish_alloc_permit.cta_group::1.sync.aligned;")
#define TCGEN05_COMMIT(mbar) \
    asm volatile("tcgen05.commit.cta_group::1.mbarrier::arrive::one.shared::cluster.b64 [%0];" \
        :: "r"((uint32_t)(mbar)) : "memory")
#define TCGEN05_FENCE_AFTER() \
    asm volatile("tcgen05.fence::after_thread_sync;" ::: "memory")
#define TCGEN05_FENCE_BEFORE() \
    asm volatile("tcgen05.fence::before_thread_sync;" ::: "memory")
#define TCGEN05_WAIT_LD() \
    asm volatile("tcgen05.wait::ld.sync.aligned;" ::: "memory")
#define TCGEN05_LD_32X32B_X16(r, tmem_addr) \
    asm volatile("tcgen05.ld.sync.aligned.32x32b.x16.b32 " \
        "{%0, %1, %2, %3, %4, %5, %6, %7, %8, %9, %10, %11, %12, %13, %14, %15}, [%16];" \
        : "=r"((r)[0]), "=r"((r)[1]), "=r"((r)[2]), "=r"((r)[3]), \
          "=r"((r)[4]), "=r"((r)[5]), "=r"((r)[6]), "=r"((r)[7]), \
          "=r"((r)[8]), "=r"((r)[9]), "=r"((r)[10]), "=r"((r)[11]), \
          "=r"((r)[12]), "=r"((r)[13]), "=r"((r)[14]), "=r"((r)[15]) \
        : "r"(tmem_addr))
#define MBARRIER_INIT(mbar, count) \
    asm volatile("mbarrier.init.shared.b64 [%0], %1;" \
        :: "r"((uint32_t)(mbar)), "r"((uint32_t)(count)) : "memory")
#define MBARRIER_WAIT_PARITY(mbar, parity) do { \
    uint32_t _m = (uint32_t)(mbar); uint32_t _p = (uint32_t)(parity); uint32_t _d; \
    asm volatile("{\n\t.reg .pred p;\n\t" \
        "mbarrier.try_wait.parity.acquire.cta.shared::cta.b64 p, [%1], %2;\n\t" \
        "selp.b32 %0, 1, 0, p;\n\t}" : "=r"(_d) : "r"(_m), "r"(_p) : "memory"); \
    if (!_d) { \
        asm volatile("{\n\t.reg .pred P1;\n\t" \
            "WL_%=:\n\t" \
            "mbarrier.try_wait.parity.acquire.cta.shared::cta.b64 P1, [%0], %1, 0x989680;\n\t" \
            "@P1 bra.uni WD_%=;\n\t" \
            "bra.uni WL_%=;\n\t" \
            "WD_%=:\n\t}" :: "r"(_m), "r"(_p) : "memory"); \
    } \
} while (0)

__device__ __forceinline__ void mma_tf32_ss(uint32_t d, uint64_t ad, uint64_t bd,
                                            uint32_t idesc, int acc) {
    asm volatile("{\n\t.reg .pred p;\n\t"
        "setp.ne.u32 p, %4, 0;\n\t"
        "tcgen05.mma.cta_group::1.kind::tf32 [%0], %1, %2, %3, {%5, %5, %5, %5}, p;\n\t"
        "}" :: "r"(d), "l"(ad), "l"(bd), "r"(idesc), "r"(acc), "r"(0u) : "memory");
}
// idesc: c=F32(1<<4), a=TF32(2<<7), b=TF32(2<<10), N=128(16<<17), M=128(8<<24)
#define IDESC_TF32 ((8u << 24) | (16u << 17) | (2u << 10) | (2u << 7) | (1u << 4))

__device__ __forceinline__ uint64_t make_desc_sw128(uint32_t addr) {
    return ((uint64_t)2 << 61) | ((uint64_t)1 << 46) | ((uint64_t)64 << 32)
         | ((uint64_t)1 << 16) | ((addr >> 4) & 0x3FFF);
}

__device__ __forceinline__ void fma2(unsigned long long& d,
                                     unsigned long long a, unsigned long long b) {
    asm("fma.rn.f32x2 %0, %1, %2, %0;" : "+l"(d) : "l"(a), "l"(b));
}
#endif // HAS_TCGEN05

// ------------------------------ norms --------------------------------------
__global__ void norm_kernel(const float* __restrict__ S, const float* __restrict__ Q) {
    int r = blockIdx.x;
    int tid = threadIdx.x;
    const float* srow = S + (size_t)r * DIM;
    const float* qrow = Q + (size_t)r * DIM;
    float s = 0.f, q = 0.f;
    for (int k = tid; k < DIM; k += 128) {
        float a = srow[k]; s = fmaf(a, a, s);
        float c = qrow[k]; q = fmaf(c, c, q);
    }
    for (int off = 16; off; off >>= 1) {
        s += __shfl_down_sync(FULLM, s, off);
        q += __shfl_down_sync(FULLM, q, off);
    }
    __shared__ float ss[4], qq[4];
    if ((tid & 31) == 0) { ss[tid >> 5] = s; qq[tid >> 5] = q; }
    __syncthreads();
    if (tid == 0) {
        d_ns[r] = sqrtf(ss[0] + ss[1] + ss[2] + ss[3]);
        d_nq[r] = sqrtf(qq[0] + qq[1] + qq[2] + qq[3]);
    }
}

// ------------------------- cost (fp32, f32x2 packed) ------------------------
__global__ void __launch_bounds__(256) cost_kernel(const float* __restrict__ S,
                                                   const float* __restrict__ Q) {
    constexpr int BN = 32, TM = 4, TN = 4;
    __shared__ float2 As2[8][NPTS];
    __shared__ float2 Bs2[8][BN];
    int b = blockIdx.y, cb = blockIdx.x;
    const float* Sb = S + (size_t)b * NPTS * DIM;
    const float* Qb = Q + (size_t)b * NPTS * DIM + (size_t)cb * BN * DIM;
    int tid = threadIdx.x;
    int aRow0 = tid >> 2, aK0 = (tid & 3) << 2;
    int aRow1 = aRow0 + 64;
    const float* Sr0 = Sb + (size_t)aRow0 * DIM + aK0;
    const float* Sr1 = Sb + (size_t)aRow1 * DIM + aK0;
    int bRow = tid >> 2;
    const float* Qr = Qb + (size_t)(bRow & 31) * DIM + aK0;
    int tx = tid & 7, ty = tid >> 3;
    int kk0 = aK0 >> 1;

#ifdef HAS_TCGEN05
    unsigned long long acc2[TM][TN];
#pragma unroll
    for (int m = 0; m < TM; m++)
#pragma unroll
        for (int n = 0; n < TN; n++) acc2[m][n] = 0ull;

    for (int k0 = 0; k0 < DIM; k0 += 16) {
        float4 a0 = *(const float4*)(Sr0 + k0);
        float4 a1 = *(const float4*)(Sr1 + k0);
        float4 b0 = (bRow < 32) ? *(const float4*)(Qr + k0) : make_float4(0, 0, 0, 0);
        __syncthreads();
        As2[kk0][aRow0] = make_float2(a0.x, a0.y);
        As2[kk0 + 1][aRow0] = make_float2(a0.z, a0.w);
        As2[kk0][aRow1] = make_float2(a1.x, a1.y);
        As2[kk0 + 1][aRow1] = make_float2(a1.z, a1.w);
        if (bRow < 32) {
            Bs2[kk0][bRow] = make_float2(b0.x, b0.y);
            Bs2[kk0 + 1][bRow] = make_float2(b0.z, b0.w);
        }
        __syncthreads();
#pragma unroll
        for (int kk = 0; kk < 8; kk++) {
            unsigned long long a2[TM], b2[TN];
#pragma unroll
            for (int m = 0; m < TM; m++)
                a2[m] = *(const unsigned long long*)&As2[kk][ty * TM + m];
#pragma unroll
            for (int n = 0; n < TN; n++)
                b2[n] = *(const unsigned long long*)&Bs2[kk][tx * TN + n];
#pragma unroll
            for (int m = 0; m < TM; m++)
#pragma unroll
                for (int n = 0; n < TN; n++) fma2(acc2[m][n], a2[m], b2[n]);
        }
    }
#pragma unroll
    for (int m = 0; m < TM; m++) {
        int r = ty * TM + m;
        float ni = d_ns[b * NPTS + r];
#pragma unroll
        for (int n = 0; n < TN; n++) {
            int c = cb * BN + tx * TN + n;
            float nj = d_nq[b * NPTS + c];
            float lo = __uint_as_float((unsigned)(acc2[m][n] & 0xffffffffull));
            float hi = __uint_as_float((unsigned)(acc2[m][n] >> 32));
            d_cost[(size_t)b * NPTS * NPTS + r * NPTS + c] = 1.0f - (lo + hi) / (ni * nj);
        }
    }
#else
    float acc[TM][TN];
#pragma unroll
    for (int m = 0; m < TM; m++)
#pragma unroll
        for (int n = 0; n < TN; n++) acc[m][n] = 0.f;
    for (int k0 = 0; k0 < DIM; k0 += 16) {
        float4 a0 = *(const float4*)(Sr0 + k0);
        float4 a1 = *(const float4*)(Sr1 + k0);
        float4 b0 = (bRow < 32) ? *(const float4*)(Qr + k0) : make_float4(0, 0, 0, 0);
        __syncthreads();
        As2[kk0][aRow0] = make_float2(a0.x, a0.y);
        As2[kk0 + 1][aRow0] = make_float2(a0.z, a0.w);
        As2[kk0][aRow1] = make_float2(a1.x, a1.y);
        As2[kk0 + 1][aRow1] = make_float2(a1.z, a1.w);
        if (bRow < 32) {
            Bs2[kk0][bRow] = make_float2(b0.x, b0.y);
            Bs2[kk0 + 1][bRow] = make_float2(b0.z, b0.w);
        }
        __syncthreads();
#pragma unroll
        for (int kk = 0; kk < 8; kk++) {
#pragma unroll
            for (int m = 0; m < TM; m++) {
                float2 a = As2[kk][ty * TM + m];
#pragma unroll
                for (int n = 0; n < TN; n++) {
                    float2 bb = Bs2[kk][tx * TN + n];
                    acc[m][n] = fmaf(a.x, bb.x, acc[m][n]);
                    acc[m][n] = fmaf(a.y, bb.y, acc[m][n]);
                }
            }
        }
    }
#pragma unroll
    for (int m = 0; m < TM; m++) {
        int r = ty * TM + m;
        float ni = d_ns[b * NPTS + r];
#pragma unroll
        for (int n = 0; n < TN; n++) {
            int c = cb * BN + tx * TN + n;
            float nj = d_nq[b * NPTS + c];
            d_cost[(size_t)b * NPTS * NPTS + r * NPTS + c] = 1.0f - acc[m][n] / (ni * nj);
        }
    }
#endif
}

// ------------------------- merged MLP GEMM ----------------------------------
// mode 0 (layer 1): X = [support; query] (A0/A1 split by by<32), C = d_h
//                   (contiguous 8192 rows), relu.
// mode 1 (layer 2): X = d_h (contiguous), C = by<32 ? C0(out0) : d_tmp,
//                   resid = by<32 ? R0(support) : R1(query), relu + resid.
// tcgen05 path: SS tf32 MMA, 2 smem stages, register prefetch, occ 2.
// smem: [0] tmem ptr, [8] mbar0, [16] mbar1, [1024 + s*32768] stage s (A 16KB, B 16KB)
// epilogue staging reuses stage 0.
#define TG_SMEM (1024 + 2 * 32768)
__global__ void __launch_bounds__(256, 2)
tgemm_kernel(const float* __restrict__ A0, const float* __restrict__ A1,
             const float* __restrict__ W, float* __restrict__ C0,
             const float* __restrict__ R0, const float* __restrict__ R1,
             int N, int K, int mode) {
    extern __shared__ char smem[];
    int tid = threadIdx.x;
    int bx = blockIdx.x, by = blockIdx.y;
    int byl = by & 31;                 // branch-local tile row (mode 1)

#ifdef HAS_TCGEN05
    uint32_t sb = smem_u32(smem);
    int wid = tid >> 5, lane = tid & 31;

    if (wid == 0) TCGEN05_ALLOC(sb, 128);
    if (tid == 0) { MBARRIER_INIT(sb + 8, 1); MBARRIER_INIT(sb + 16, 1); }
    __syncthreads();
    uint32_t tmem;
    asm volatile("ld.shared.b32 %0, [%1];" : "=r"(tmem) : "r"(sb));

    const float* ap[4]; const float* bp[4]; uint32_t soff[4];
#pragma unroll
    for (int i = 0; i < 4; i++) {
        int idx = tid + i * 256;
        int r = idx >> 3, kg = idx & 7;
        const float* Abase;
        if (mode == 0)
            Abase = (by < 32) ? (A0 + (size_t)by * NPTS * K)
                              : (A1 + (size_t)(by - 32) * NPTS * K);
        else
            Abase = d_h + (size_t)by * NPTS * K;
        ap[i] = Abase + (size_t)r * K + kg * 4;
        bp[i] = W + (size_t)(bx * NPTS + r) * K + kg * 4;
        soff[i] = SW128((uint32_t)(r * 128 + kg * 16));
    }
    uint64_t adesc[2] = { make_desc_sw128(sb + 1024), make_desc_sw128(sb + 1024 + 32768) };
    uint64_t bdesc[2] = { make_desc_sw128(sb + 17408), make_desc_sw128(sb + 17408 + 32768) };

    const int NCH = K / KC;
    float4 a4[4], b4[4], an[4], bn[4];
#pragma unroll
    for (int i = 0; i < 4; i++) {       // preload chunk 0
        a4[i] = *(const float4*)(ap[i]);
        b4[i] = *(const float4*)(bp[i]);
    }
    for (int c = 0; c < NCH; c++) {
        int s = c & 1;
        uint32_t abase = 1024 + (uint32_t)s * 32768;
        if (c + 1 < NCH) {               // prefetch chunk c+1 (before any wait)
#pragma unroll
            for (int i = 0; i < 4; i++) {
                an[i] = *(const float4*)(ap[i] + (c + 1) * KC);
                bn[i] = *(const float4*)(bp[i] + (c + 1) * KC);
            }
        }
        if (c >= 2) MBARRIER_WAIT_PARITY(sb + 8 + 8 * s, ((c >> 1) - 1) & 1);
#pragma unroll
        for (int i = 0; i < 4; i++) {
            float4 t;
            t.x = to_tf32(a4[i].x); t.y = to_tf32(a4[i].y);
            t.z = to_tf32(a4[i].z); t.w = to_tf32(a4[i].w);
            *(float4*)(smem + abase + soff[i]) = t;
            t.x = to_tf32(b4[i].x); t.y = to_tf32(b4[i].y);
            t.z = to_tf32(b4[i].z); t.w = to_tf32(b4[i].w);
            *(float4*)(smem + abase + 16384 + soff[i]) = t;
        }
        __syncthreads();
        if (tid == 0) {
            asm volatile("fence.proxy.async.shared::cta;" ::: "memory");
#pragma unroll
            for (int k = 0; k < 4; k++)
                mma_tf32_ss(tmem, adesc[s] + k * 2, bdesc[s] + k * 2, IDESC_TF32, (c | k) != 0);
            TCGEN05_COMMIT(sb + 8 + 8 * s);
        }
#pragma unroll
        for (int i = 0; i < 4; i++) { a4[i] = an[i]; b4[i] = bn[i]; }
    }
    // final commit tracks ALL prior MMAs issued by thread 0
    MBARRIER_WAIT_PARITY(sb + 8 + 8 * ((NCH - 1) & 1), ((NCH - 1) >> 1) & 1);
    TCGEN05_FENCE_AFTER();

    // ------------------ epilogue: 8 groups of 16 columns ------------------
    float* St = (float*)(smem + 1024);     // reuse dead stage-0 buffer
    int wrow = tid >> 1, wc0 = (tid & 1) * 8;
    float* Cb; const float* rres = nullptr;
    if (mode == 0) {
        Cb = d_h + (size_t)(by * NPTS + wrow) * N;
    } else {
        size_t lr = (size_t)(byl * NPTS + wrow);
        Cb = ((by < 32) ? C0 : d_tmp) + lr * N;
        rres = ((by < 32) ? R0 : R1) + lr * N;
    }
    for (int g = 0; g < 8; g++) {
        if (tid < 128) {
            uint32_t r16[16];
            TCGEN05_LD_32X32B_X16(r16, tmem + g * 16);
            TCGEN05_WAIT_LD();
            int row = wid * 32 + lane;
#pragma unroll
            for (int cc = 0; cc < 16; cc++)
                St[row * 17 + cc] = __uint_as_float(r16[cc]);
        }
        __syncthreads();
        {
            int col = bx * NPTS + g * 16 + wc0;
            float o[8];
#pragma unroll
            for (int cc = 0; cc < 8; cc++) {
                float f = fmaxf(St[wrow * 17 + wc0 + cc], 0.f);
                if (mode == 1) f += rres[col + cc];
                o[cc] = f;
            }
            *(float4*)(Cb + col)     = make_float4(o[0], o[1], o[2], o[3]);
            *(float4*)(Cb + col + 4) = make_float4(o[4], o[5], o[6], o[7]);
        }
        __syncthreads();
    }
    TCGEN05_FENCE_BEFORE();
    if (wid == 0) { TCGEN05_RELINQUISH(); TCGEN05_DEALLOC(tmem, 128); }

#else  // ---------------- FFMA fallback (generic PTX pass) ------------------
    constexpr int BK = 16, TM = 8, TN = 8;
    float* As = (float*)smem;
    float* Bs = (float*)(smem + 8192);
    int aRow0 = tid >> 2, aK0 = (tid & 3) << 2;
    int aRow1 = aRow0 + 64;
    const float* Abase;
    if (mode == 0)
        Abase = (by < 32) ? (A0 + (size_t)by * NPTS * K)
                          : (A1 + (size_t)(by - 32) * NPTS * K);
    else
        Abase = d_h + (size_t)by * NPTS * K;
    const float* Xr0 = Abase + (size_t)aRow0 * K + aK0;
    const float* Xr1 = Abase + (size_t)aRow1 * K + aK0;
    const float* Wr0 = W + (size_t)(bx * NPTS + aRow0) * K + aK0;
    const float* Wr1 = W + (size_t)(bx * NPTS + aRow1) * K + aK0;
    int tx = tid & 15, ty = tid >> 4;
    float acc[TM][TN];
#pragma unroll
    for (int m = 0; m < TM; m++)
#pragma unroll
        for (int n = 0; n < TN; n++) acc[m][n] = 0.f;
    for (int k0 = 0; k0 < K; k0 += BK) {
        float4 a0 = *(const float4*)(Xr0 + k0);
        float4 a1 = *(const float4*)(Xr1 + k0);
        float4 b0 = *(const float4*)(Wr0 + k0);
        float4 b1 = *(const float4*)(Wr1 + k0);
        __syncthreads();
        As[(aK0 + 0) * 128 + aRow0] = a0.x; As[(aK0 + 1) * 128 + aRow0] = a0.y;
        As[(aK0 + 2) * 128 + aRow0] = a0.z; As[(aK0 + 3) * 128 + aRow0] = a0.w;
        As[(aK0 + 0) * 128 + aRow1] = a1.x; As[(aK0 + 1) * 128 + aRow1] = a1.y;
        As[(aK0 + 2) * 128 + aRow1] = a1.z; As[(aK0 + 3) * 128 + aRow1] = a1.w;
        Bs[(aK0 + 0) * 128 + aRow0] = b0.x; Bs[(aK0 + 1) * 128 + aRow0] = b0.y;
        Bs[(aK0 + 2) * 128 + aRow0] = b0.z; Bs[(aK0 + 3) * 128 + aRow0] = b0.w;
        Bs[(aK0 + 0) * 128 + aRow1] = b1.x; Bs[(aK0 + 1) * 128 + aRow1] = b1.y;
        Bs[(aK0 + 2) * 128 + aRow1] = b1.z; Bs[(aK0 + 3) * 128 + aRow1] = b1.w;
        __syncthreads();
#pragma unroll
        for (int k = 0; k < BK; k++) {
#pragma unroll
            for (int m = 0; m < TM; m++) {
                float a = As[k * 128 + ty * TM + m];
#pragma unroll
                for (int n = 0; n < TN; n++)
                    acc[m][n] = fmaf(a, Bs[k * 128 + tx * TN + n], acc[m][n]);
            }
        }
    }
    int lr0 = (mode == 0) ? (by * NPTS + ty * TM) : (byl * NPTS + ty * TM);
    int col0 = bx * NPTS + tx * TN;
    float* Csel = (mode == 0) ? d_h : ((by < 32) ? C0 : d_tmp);
    const float* Rsel = (mode == 1) ? ((by < 32) ? R0 : R1) : nullptr;
#pragma unroll
    for (int m = 0; m < TM; m++) {
        int gr = lr0 + m;
        const float* rr = Rsel ? (Rsel + (size_t)gr * N) : nullptr;
#pragma unroll
        for (int n = 0; n < TN; n++) {
            float vv = fmaxf(acc[m][n], 0.f);
            if (rr) vv += rr[col0 + n];
            Csel[(size_t)gr * N + col0 + n] = vv;
        }
    }
#endif
}

// --------------------------- JV Hungarian (fast) ----------------------------
__device__ __forceinline__ unsigned fkey(float f) {
    unsigned u = __float_as_uint(f);
    return (u & 0x80000000u) ? ~u : (u | 0x80000000u);
}
__device__ __forceinline__ float fuk(unsigned k) {
    k = (k & 0x80000000u) ? (k & 0x7fffffffu) : ~k;
    return __uint_as_float(k);
}

__global__ void lap_kernel() {
    extern __shared__ float csh[];            // [128][128] cost, 64KB
    __shared__ float u_sh[NPTS];
    __shared__ int   roc_sh[NPTS];
    __shared__ int   cor_sh[NPTS];
    __shared__ int   way_sh[NPTS];
    __shared__ int   im_sh[NPTS];
    int b = blockIdx.x, lane = threadIdx.x;

    const float4* src = (const float4*)(d_cost + (size_t)b * NPTS * NPTS);
    float4* dst = (float4*)csh;
    for (int i = lane; i < NPTS * NPTS / 4; i += 32) dst[i] = src[i];
    for (int r = lane; r < NPTS; r += 32) { u_sh[r] = 0.f; cor_sh[r] = -1; }
    __syncwarp();

    float v[4] = {INFINITY, INFINITY, INFINITY, INFINITY};
    int im[4] = {0, 0, 0, 0};
    for (int i = 0; i < NPTS; i++) {
        float4 c4 = *(const float4*)(csh + i * NPTS + 4 * lane);
        float cc[4] = {c4.x, c4.y, c4.z, c4.w};
#pragma unroll
        for (int t = 0; t < 4; t++)
            if (cc[t] < v[t]) { v[t] = cc[t]; im[t] = i; }
    }
#pragma unroll
    for (int t = 0; t < 4; t++) im_sh[4 * lane + t] = im[t];
    __syncwarp();
    if (lane == 0) {
        for (int j = 0; j < NPTS; j++) {
            int i = im_sh[j];
            if (cor_sh[i] < 0) { cor_sh[i] = j; roc_sh[j] = i; }
            else roc_sh[j] = -1;
        }
    }
    __syncwarp();

    for (int i = 0; i < NPTS; i++) {
        if (cor_sh[i] >= 0) continue;
        float dist[4] = {INFINITY, INFINITY, INFINITY, INFINITY};
        int usedm = 0;
        int i0 = i, j0 = -1, jfin = -1;
        float D = 0.f, ui0 = u_sh[i0];
        for (int it = 0; it < NPTS + 2; it++) {
            float4 c4 = *(const float4*)(csh + i0 * NPTS + 4 * lane);
            float cc[4] = {c4.x, c4.y, c4.z, c4.w};
            float best = INFINITY; int jb = 0x7fffffff;
#pragma unroll
            for (int t = 0; t < 4; t++) {
                if (!((usedm >> t) & 1)) {
                    float nd = D + cc[t] - ui0 - v[t];
                    if (nd < dist[t]) { dist[t] = nd; way_sh[4 * lane + t] = j0; }
                    if (dist[t] < best) { best = dist[t]; jb = 4 * lane + t; }
                }
            }
            unsigned key = fkey(best);
            unsigned kmin = __reduce_min_sync(FULLM, key);
            unsigned bal = __ballot_sync(FULLM, key == kmin);
            int srcl = __ffs(bal) - 1;
            int j1 = __shfl_sync(FULLM, jb, srcl);
            D = fuk(kmin);
            int i1 = roc_sh[j1];
            if (i1 < 0) { jfin = j1; break; }
            { int ol = j1 >> 2, ot = j1 & 3; if (lane == ol) usedm |= 1 << ot; }
            i0 = i1; ui0 = u_sh[i0]; j0 = j1;
        }
        __syncwarp();
#pragma unroll
        for (int t = 0; t < 4; t++) {
            if ((usedm >> t) & 1) {
                int j = 4 * lane + t;
                float dd = D - dist[t];
                v[t] -= dd;
                u_sh[roc_sh[j]] += dd;
            }
        }
        if (lane == 0) u_sh[i] += D;
        __syncwarp();
        if (lane == 0) {
            int j = jfin;
            while (way_sh[j] >= 0) { int jp = way_sh[j]; roc_sh[j] = roc_sh[jp]; j = jp; }
            roc_sh[j] = i;
        }
        __syncwarp();
    }
    for (int j = lane; j < NPTS; j += 32)
        d_perm[b * NPTS + roc_sh[j]] = b * NPTS + j;
}

// --------------------------- out1 permutation gather ------------------------
__global__ void gather_kernel(float* __restrict__ out1) {
    int g = blockIdx.x;
    int src = d_perm[g];
    const float4* s = (const float4*)(d_tmp + (size_t)src * DIM);
    float4* d = (float4*)(out1 + (size_t)g * DIM);
    for (int k = threadIdx.x; k < DIM / 4; k += 256) d[k] = s[k];
}

// ------------------------------ launch --------------------------------------
static cudaStream_t g_s2 = nullptr;
static cudaEvent_t g_evF = nullptr, g_evJ = nullptr;

extern "C" void kernel_launch(void* const* d_in, const int* in_sizes, int n_in,
                              void* d_out, int out_size) {
    const float* support = (const float*)d_in[0];
    const float* query   = (const float*)d_in[1];
    const float* W1      = (const float*)d_in[2];   // [1024, 2048]
    const float* W2      = (const float*)d_in[3];   // [2048, 1024]
    float* out0 = (float*)d_out;
    float* out1 = out0 + (size_t)MROWS * DIM;

    if (!g_s2) {   // one-time resource creation (first call is uncaptured)
        cudaStreamCreateWithFlags(&g_s2, cudaStreamNonBlocking);
        cudaEventCreateWithFlags(&g_evF, cudaEventDisableTiming);
        cudaEventCreateWithFlags(&g_evJ, cudaEventDisableTiming);
        cudaFuncSetAttribute(lap_kernel, cudaFuncAttributeMaxDynamicSharedMemorySize, 65536);
        cudaFuncSetAttribute(tgemm_kernel, cudaFuncAttributeMaxDynamicSharedMemorySize, TG_SMEM);
    }

    // fork: GEMM chain (independent of matching) runs on s2 concurrently
    cudaEventRecord(g_evF, 0);
    cudaStreamWaitEvent(g_s2, g_evF, 0);

    // stream 0: matching path
    norm_kernel<<<MROWS, 128>>>(support, query);
    cost_kernel<<<dim3(4, BATCH), 256>>>(support, query);
    lap_kernel<<<BATCH, 32, 65536>>>();

    // stream s2: MLP, both branches merged per layer (perm commutes with MLP)
    tgemm_kernel<<<dim3(HID / 128, 2 * BATCH), 256, TG_SMEM, g_s2>>>(
        support, query, W1, nullptr, nullptr, nullptr, HID, DIM, 0);
    tgemm_kernel<<<dim3(DIM / 128, 2 * BATCH), 256, TG_SMEM, g_s2>>>(
        nullptr, nullptr, W2, out0, support, query, DIM, HID, 1);

    // join, then permute out1
    cudaEventRecord(g_evJ, g_s2);
    cudaStreamWaitEvent(0, g_evJ, 0);
    gather_kernel<<<MROWS, 256>>>(out1);
}

// round 10
// speedup vs baseline: 8.6749x; 1.2862x over previous
#include <cuda_runtime.h>
#include <math.h>
#include <stdint.h>

#define BATCH 32
#define NPTS  128
#define DIM   2048
#define HID   1024
#define MROWS (BATCH * NPTS)   // 4096
#define KC    32               // K floats per smem chunk (= 128B SW128 atom row)
#define BNT   256              // GEMM N tile
#define FULLM 0xffffffffu

// tcgen05 / f32x2 only exist in the sm_103a (arch-specific) compilation pass.
#ifdef __CUDA_ARCH_FEAT_SM103_ALL
#define HAS_TCGEN05 1
#endif

// ------------------------------ scratch ------------------------------------
__device__ float d_cost[BATCH * NPTS * NPTS];
__device__ int   d_perm[MROWS];                 // d_perm[g] = global src row of out1 row g
__device__ float d_h[2u * MROWS * HID];         // hidden acts: rows 0..4095 support, 4096..8191 query
__device__ float d_tmp[(size_t)MROWS * DIM];    // query + mlp(query), unpermuted

// ------------------------------ PTX helpers ---------------------------------
__device__ __forceinline__ uint32_t smem_u32(const void* p) {
    uint32_t a;
    asm("{ .reg .u64 t; cvta.to.shared.u64 t, %1; cvt.u32.u64 %0, t; }"
        : "=r"(a) : "l"(p));
    return a;
}
#define SW128(o) ((o) ^ (((o) >> 3) & 0x70))

#ifdef HAS_TCGEN05
__device__ __forceinline__ float to_tf32(float x) {
    float r; asm("cvt.rna.tf32.f32 %0, %1;" : "=f"(r) : "f"(x)); return r;
}
#define TCGEN05_ALLOC(smem_addr, nCols) \
    asm volatile("tcgen05.alloc.cta_group::1.sync.aligned.shared::cta.b32 [%0], %1;" \
        :: "r"((uint32_t)(smem_addr)), "r"((uint32_t)(nCols)) : "memory")
#define TCGEN05_DEALLOC(tmem_addr, nCols) \
    asm volatile("tcgen05.dealloc.cta_group::1.sync.aligned.b32 %0, %1;" \
        :: "r"(tmem_addr), "r"((uint32_t)(nCols)))
#define TCGEN05_RELINQUISH() \
    asm volatile("tcgen05.relinquish_alloc_permit.cta_group::1.sync.aligned;")
#define TCGEN05_COMMIT(mbar) \
    asm volatile("tcgen05.commit.cta_group::1.mbarrier::arrive::one.shared::cluster.b64 [%0];" \
        :: "r"((uint32_t)(mbar)) : "memory")
#define TCGEN05_FENCE_AFTER() \
    asm volatile("tcgen05.fence::after_thread_sync;" ::: "memory")
#define TCGEN05_FENCE_BEFORE() \
    asm volatile("tcgen05.fence::before_thread_sync;" ::: "memory")
#define TCGEN05_WAIT_LD() \
    asm volatile("tcgen05.wait::ld.sync.aligned;" ::: "memory")
#define TCGEN05_LD_32X32B_X16(r, tmem_addr) \
    asm volatile("tcgen05.ld.sync.aligned.32x32b.x16.b32 " \
        "{%0, %1, %2, %3, %4, %5, %6, %7, %8, %9, %10, %11, %12, %13, %14, %15}, [%16];" \
        : "=r"((r)[0]), "=r"((r)[1]), "=r"((r)[2]), "=r"((r)[3]), \
          "=r"((r)[4]), "=r"((r)[5]), "=r"((r)[6]), "=r"((r)[7]), \
          "=r"((r)[8]), "=r"((r)[9]), "=r"((r)[10]), "=r"((r)[11]), \
          "=r"((r)[12]), "=r"((r)[13]), "=r"((r)[14]), "=r"((r)[15]) \
        : "r"(tmem_addr))
#define MBARRIER_INIT(mbar, count) \
    asm volatile("mbarrier.init.shared.b64 [%0], %1;" \
        :: "r"((uint32_t)(mbar)), "r"((uint32_t)(count)) : "memory")
#define MBARRIER_WAIT_PARITY(mbar, parity) do { \
    uint32_t _m = (uint32_t)(mbar); uint32_t _p = (uint32_t)(parity); uint32_t _d; \
    asm volatile("{\n\t.reg .pred p;\n\t" \
        "mbarrier.try_wait.parity.acquire.cta.shared::cta.b64 p, [%1], %2;\n\t" \
        "selp.b32 %0, 1, 0, p;\n\t}" : "=r"(_d) : "r"(_m), "r"(_p) : "memory"); \
    if (!_d) { \
        asm volatile("{\n\t.reg .pred P1;\n\t" \
            "WL_%=:\n\t" \
            "mbarrier.try_wait.parity.acquire.cta.shared::cta.b64 P1, [%0], %1, 0x989680;\n\t" \
            "@P1 bra.uni WD_%=;\n\t" \
            "bra.uni WL_%=;\n\t" \
            "WD_%=:\n\t}" :: "r"(_m), "r"(_p) : "memory"); \
    } \
} while (0)

__device__ __forceinline__ void mma_tf32_ss(uint32_t d, uint64_t ad, uint64_t bd,
                                            uint32_t idesc, int acc) {
    asm volatile("{\n\t.reg .pred p;\n\t"
        "setp.ne.u32 p, %4, 0;\n\t"
        "tcgen05.mma.cta_group::1.kind::tf32 [%0], %1, %2, %3, {%5, %5, %5, %5}, p;\n\t"
        "}" :: "r"(d), "l"(ad), "l"(bd), "r"(idesc), "r"(acc), "r"(0u) : "memory");
}
// idesc: c=F32(1<<4), a=TF32(2<<7), b=TF32(2<<10), N=256(32<<17), M=128(8<<24)
#define IDESC_TF32 ((8u << 24) | ((BNT / 8u) << 17) | (2u << 10) | (2u << 7) | (1u << 4))

__device__ __forceinline__ uint64_t make_desc_sw128(uint32_t addr) {
    return ((uint64_t)2 << 61) | ((uint64_t)1 << 46) | ((uint64_t)64 << 32)
         | ((uint64_t)1 << 16) | ((addr >> 4) & 0x3FFF);
}

__device__ __forceinline__ void fma2(unsigned long long& d,
                                     unsigned long long a, unsigned long long b) {
    asm("fma.rn.f32x2 %0, %1, %2, %0;" : "+l"(d) : "l"(a), "l"(b));
}
#endif // HAS_TCGEN05

// ------------------------- cost (fp32) + fused norms -------------------------
// grid (4, BATCH): 128x32 output tile, K=2048. Norms accumulated on the fly
// from the streamed rows (4-lane shfl reduce), so no separate norm kernel.
__global__ void __launch_bounds__(256) cost_kernel(const float* __restrict__ S,
                                                   const float* __restrict__ Q) {
    constexpr int BN = 32, TM = 4, TN = 4;
    __shared__ float2 As2[8][NPTS];
    __shared__ float2 Bs2[8][BN];
    __shared__ float ns_sh[NPTS];
    __shared__ float nq_sh[BN];
    int b = blockIdx.y, cb = blockIdx.x;
    const float* Sb = S + (size_t)b * NPTS * DIM;
    const float* Qb = Q + (size_t)b * NPTS * DIM + (size_t)cb * BN * DIM;
    int tid = threadIdx.x;
    int aRow0 = tid >> 2, aK0 = (tid & 3) << 2;
    int aRow1 = aRow0 + 64;
    const float* Sr0 = Sb + (size_t)aRow0 * DIM + aK0;
    const float* Sr1 = Sb + (size_t)aRow1 * DIM + aK0;
    int bRow = tid >> 2;
    const float* Qr = Qb + (size_t)(bRow & 31) * DIM + aK0;
    int tx = tid & 7, ty = tid >> 3;
    int kk0 = aK0 >> 1;
    float sn0 = 0.f, sn1 = 0.f, qn = 0.f;

#ifdef HAS_TCGEN05
    unsigned long long acc2[TM][TN];
#pragma unroll
    for (int m = 0; m < TM; m++)
#pragma unroll
        for (int n = 0; n < TN; n++) acc2[m][n] = 0ull;

    for (int k0 = 0; k0 < DIM; k0 += 16) {
        float4 a0 = *(const float4*)(Sr0 + k0);
        float4 a1 = *(const float4*)(Sr1 + k0);
        float4 b0 = (bRow < 32) ? *(const float4*)(Qr + k0) : make_float4(0, 0, 0, 0);
        sn0 = fmaf(a0.x, a0.x, sn0); sn0 = fmaf(a0.y, a0.y, sn0);
        sn0 = fmaf(a0.z, a0.z, sn0); sn0 = fmaf(a0.w, a0.w, sn0);
        sn1 = fmaf(a1.x, a1.x, sn1); sn1 = fmaf(a1.y, a1.y, sn1);
        sn1 = fmaf(a1.z, a1.z, sn1); sn1 = fmaf(a1.w, a1.w, sn1);
        qn  = fmaf(b0.x, b0.x, qn);  qn  = fmaf(b0.y, b0.y, qn);
        qn  = fmaf(b0.z, b0.z, qn);  qn  = fmaf(b0.w, b0.w, qn);
        __syncthreads();
        As2[kk0][aRow0] = make_float2(a0.x, a0.y);
        As2[kk0 + 1][aRow0] = make_float2(a0.z, a0.w);
        As2[kk0][aRow1] = make_float2(a1.x, a1.y);
        As2[kk0 + 1][aRow1] = make_float2(a1.z, a1.w);
        if (bRow < 32) {
            Bs2[kk0][bRow] = make_float2(b0.x, b0.y);
            Bs2[kk0 + 1][bRow] = make_float2(b0.z, b0.w);
        }
        __syncthreads();
#pragma unroll
        for (int kk = 0; kk < 8; kk++) {
            unsigned long long a2[TM], b2[TN];
#pragma unroll
            for (int m = 0; m < TM; m++)
                a2[m] = *(const unsigned long long*)&As2[kk][ty * TM + m];
#pragma unroll
            for (int n = 0; n < TN; n++)
                b2[n] = *(const unsigned long long*)&Bs2[kk][tx * TN + n];
#pragma unroll
            for (int m = 0; m < TM; m++)
#pragma unroll
                for (int n = 0; n < TN; n++) fma2(acc2[m][n], a2[m], b2[n]);
        }
    }
    // 4-lane reduce (threads 4r..4r+3 share a row)
    sn0 += __shfl_xor_sync(FULLM, sn0, 1); sn0 += __shfl_xor_sync(FULLM, sn0, 2);
    sn1 += __shfl_xor_sync(FULLM, sn1, 1); sn1 += __shfl_xor_sync(FULLM, sn1, 2);
    qn  += __shfl_xor_sync(FULLM, qn, 1);  qn  += __shfl_xor_sync(FULLM, qn, 2);
    if ((tid & 3) == 0) {
        ns_sh[aRow0] = sn0; ns_sh[aRow1] = sn1;
        if (bRow < 32) nq_sh[bRow] = qn;
    }
    __syncthreads();
#pragma unroll
    for (int m = 0; m < TM; m++) {
        int r = ty * TM + m;
        float ni = sqrtf(ns_sh[r]);
#pragma unroll
        for (int n = 0; n < TN; n++) {
            int cl = tx * TN + n;
            float nj = sqrtf(nq_sh[cl]);
            float lo = __uint_as_float((unsigned)(acc2[m][n] & 0xffffffffull));
            float hi = __uint_as_float((unsigned)(acc2[m][n] >> 32));
            d_cost[(size_t)b * NPTS * NPTS + r * NPTS + cb * BN + cl] =
                1.0f - (lo + hi) / (ni * nj);
        }
    }
#else
    float acc[TM][TN];
#pragma unroll
    for (int m = 0; m < TM; m++)
#pragma unroll
        for (int n = 0; n < TN; n++) acc[m][n] = 0.f;
    for (int k0 = 0; k0 < DIM; k0 += 16) {
        float4 a0 = *(const float4*)(Sr0 + k0);
        float4 a1 = *(const float4*)(Sr1 + k0);
        float4 b0 = (bRow < 32) ? *(const float4*)(Qr + k0) : make_float4(0, 0, 0, 0);
        sn0 = fmaf(a0.x, a0.x, sn0); sn0 = fmaf(a0.y, a0.y, sn0);
        sn0 = fmaf(a0.z, a0.z, sn0); sn0 = fmaf(a0.w, a0.w, sn0);
        sn1 = fmaf(a1.x, a1.x, sn1); sn1 = fmaf(a1.y, a1.y, sn1);
        sn1 = fmaf(a1.z, a1.z, sn1); sn1 = fmaf(a1.w, a1.w, sn1);
        qn  = fmaf(b0.x, b0.x, qn);  qn  = fmaf(b0.y, b0.y, qn);
        qn  = fmaf(b0.z, b0.z, qn);  qn  = fmaf(b0.w, b0.w, qn);
        __syncthreads();
        As2[kk0][aRow0] = make_float2(a0.x, a0.y);
        As2[kk0 + 1][aRow0] = make_float2(a0.z, a0.w);
        As2[kk0][aRow1] = make_float2(a1.x, a1.y);
        As2[kk0 + 1][aRow1] = make_float2(a1.z, a1.w);
        if (bRow < 32) {
            Bs2[kk0][bRow] = make_float2(b0.x, b0.y);
            Bs2[kk0 + 1][bRow] = make_float2(b0.z, b0.w);
        }
        __syncthreads();
#pragma unroll
        for (int kk = 0; kk < 8; kk++) {
#pragma unroll
            for (int m = 0; m < TM; m++) {
                float2 a = As2[kk][ty * TM + m];
#pragma unroll
                for (int n = 0; n < TN; n++) {
                    float2 bb = Bs2[kk][tx * TN + n];
                    acc[m][n] = fmaf(a.x, bb.x, acc[m][n]);
                    acc[m][n] = fmaf(a.y, bb.y, acc[m][n]);
                }
            }
        }
    }
    sn0 += __shfl_xor_sync(FULLM, sn0, 1); sn0 += __shfl_xor_sync(FULLM, sn0, 2);
    sn1 += __shfl_xor_sync(FULLM, sn1, 1); sn1 += __shfl_xor_sync(FULLM, sn1, 2);
    qn  += __shfl_xor_sync(FULLM, qn, 1);  qn  += __shfl_xor_sync(FULLM, qn, 2);
    if ((tid & 3) == 0) {
        ns_sh[aRow0] = sn0; ns_sh[aRow1] = sn1;
        if (bRow < 32) nq_sh[bRow] = qn;
    }
    __syncthreads();
#pragma unroll
    for (int m = 0; m < TM; m++) {
        int r = ty * TM + m;
        float ni = sqrtf(ns_sh[r]);
#pragma unroll
        for (int n = 0; n < TN; n++) {
            int cl = tx * TN + n;
            float nj = sqrtf(nq_sh[cl]);
            d_cost[(size_t)b * NPTS * NPTS + r * NPTS + cb * BN + cl] =
                1.0f - acc[m][n] / (ni * nj);
        }
    }
#endif
}

// ------------------------- merged MLP GEMM (128 x 256 tile) ------------------
// mode 0 (layer 1): X = [support; query] (A0/A1 split by by<32), C = d_h, relu.
// mode 1 (layer 2): X = d_h, C = by<32 ? C0(out0) : d_tmp,
//                   resid = by<32 ? R0(support) : R1(query), relu + resid.
// tcgen05 path: SS tf32 MMA N=256, 2 smem stages (A 16KB + B 32KB each).
// smem: [0] tmem ptr, [8] mbar0, [16] mbar1, [1024 + s*49152] stage s.
#define TG_SMEM (1024 + 2 * 49152)
__global__ void __launch_bounds__(256, 2)
tgemm_kernel(const float* __restrict__ A0, const float* __restrict__ A1,
             const float* __restrict__ W, float* __restrict__ C0,
             const float* __restrict__ R0, const float* __restrict__ R1,
             int N, int K, int mode) {
    extern __shared__ char smem[];
    int tid = threadIdx.x;
    int bx = blockIdx.x, by = blockIdx.y;
    int byl = by & 31;                 // branch-local tile row (mode 1)
    const float* Abase;
    if (mode == 0)
        Abase = (by < 32) ? (A0 + (size_t)by * NPTS * K)
                          : (A1 + (size_t)(by - 32) * NPTS * K);
    else
        Abase = d_h + (size_t)by * NPTS * K;

#ifdef HAS_TCGEN05
    uint32_t sb = smem_u32(smem);
    int wid = tid >> 5, lane = tid & 31;

    if (wid == 0) TCGEN05_ALLOC(sb, BNT);
    if (tid == 0) { MBARRIER_INIT(sb + 8, 1); MBARRIER_INIT(sb + 16, 1); }
    __syncthreads();
    uint32_t tmem;
    asm volatile("ld.shared.b32 %0, [%1];" : "=r"(tmem) : "r"(sb));

    // slot structure: slot i covers row (tid>>3)+32*i, kgroup tid&7 (float4).
    // swizzled offset stride per i is exactly +4096 (r&7 invariant under +32).
    int r0 = tid >> 3, kg = tid & 7;
    const float* ap0 = Abase + (size_t)r0 * K + kg * 4;
    const float* bp0 = W + (size_t)(bx * BNT + r0) * K + kg * 4;
    uint32_t soff0 = SW128((uint32_t)(r0 * 128 + kg * 16));
    size_t astep = (size_t)32 * K;

    uint64_t adesc[2] = { make_desc_sw128(sb + 1024),
                          make_desc_sw128(sb + 1024 + 49152) };
    uint64_t bdesc[2] = { make_desc_sw128(sb + 1024 + 16384),
                          make_desc_sw128(sb + 1024 + 49152 + 16384) };

    const int NCH = K / KC;
    for (int c = 0; c < NCH; c++) {
        int s = c & 1;
        uint32_t stg = 1024 + (uint32_t)s * 49152;
        float4 a4[4], b4[8];
#pragma unroll
        for (int i = 0; i < 4; i++) a4[i] = *(const float4*)(ap0 + i * astep + c * KC);
#pragma unroll
        for (int i = 0; i < 8; i++) b4[i] = *(const float4*)(bp0 + i * astep + c * KC);
        if (c >= 2) MBARRIER_WAIT_PARITY(sb + 8 + 8 * s, ((c >> 1) - 1) & 1);
#pragma unroll
        for (int i = 0; i < 4; i++) {
            float4 t;
            t.x = to_tf32(a4[i].x); t.y = to_tf32(a4[i].y);
            t.z = to_tf32(a4[i].z); t.w = to_tf32(a4[i].w);
            *(float4*)(smem + stg + soff0 + i * 4096u) = t;
        }
#pragma unroll
        for (int i = 0; i < 8; i++) {
            float4 t;
            t.x = to_tf32(b4[i].x); t.y = to_tf32(b4[i].y);
            t.z = to_tf32(b4[i].z); t.w = to_tf32(b4[i].w);
            *(float4*)(smem + stg + 16384 + soff0 + i * 4096u) = t;
        }
        __syncthreads();
        if (tid == 0) {
            asm volatile("fence.proxy.async.shared::cta;" ::: "memory");
#pragma unroll
            for (int k = 0; k < 4; k++)   // 4 x K=8 MMAs cover the 32-float chunk
                mma_tf32_ss(tmem, adesc[s] + k * 2, bdesc[s] + k * 2, IDESC_TF32, (c | k) != 0);
            TCGEN05_COMMIT(sb + 8 + 8 * s);
        }
    }
    MBARRIER_WAIT_PARITY(sb + 8 + 8 * ((NCH - 1) & 1), ((NCH - 1) >> 1) & 1);
    TCGEN05_FENCE_AFTER();

    // ------------------ epilogue: 16 groups of 16 columns ------------------
    float* St = (float*)(smem + 1024);     // reuse dead stage-0 buffer
    int wrow = tid >> 1, wc0 = (tid & 1) * 8;
    float* Cb; const float* rres = nullptr;
    if (mode == 0) {
        Cb = d_h + (size_t)(by * NPTS + wrow) * N;
    } else {
        size_t lr = (size_t)(byl * NPTS + wrow);
        Cb = ((by < 32) ? C0 : d_tmp) + lr * N;
        rres = ((by < 32) ? R0 : R1) + lr * N;
    }
    for (int g = 0; g < BNT / 16; g++) {
        if (tid < 128) {
            uint32_t r16[16];
            TCGEN05_LD_32X32B_X16(r16, tmem + g * 16);
            TCGEN05_WAIT_LD();
            int row = wid * 32 + lane;
#pragma unroll
            for (int cc = 0; cc < 16; cc++)
                St[row * 17 + cc] = __uint_as_float(r16[cc]);
        }
        __syncthreads();
        {
            int col = bx * BNT + g * 16 + wc0;
            float o[8];
#pragma unroll
            for (int cc = 0; cc < 8; cc++) {
                float f = fmaxf(St[wrow * 17 + wc0 + cc], 0.f);
                if (mode == 1) f += rres[col + cc];
                o[cc] = f;
            }
            *(float4*)(Cb + col)     = make_float4(o[0], o[1], o[2], o[3]);
            *(float4*)(Cb + col + 4) = make_float4(o[4], o[5], o[6], o[7]);
        }
        __syncthreads();
    }
    TCGEN05_FENCE_BEFORE();
    if (wid == 0) { TCGEN05_RELINQUISH(); TCGEN05_DEALLOC(tmem, BNT); }

#else  // ---------------- FFMA fallback (generic PTX pass; never runs) -------
    constexpr int BK = 16, TM = 8, TN = 8;
    float* As = (float*)smem;
    float* Bs = (float*)(smem + 8192);
    int aRow0 = tid >> 2, aK0 = (tid & 3) << 2;
    int aRow1 = aRow0 + 64;
    const float* Xr0 = Abase + (size_t)aRow0 * K + aK0;
    const float* Xr1 = Abase + (size_t)aRow1 * K + aK0;
    int tx = tid & 15, ty = tid >> 4;
    for (int nh = 0; nh < BNT / 128; nh++) {
        int colbase = bx * BNT + nh * 128;
        const float* Wr0 = W + (size_t)(colbase + aRow0) * K + aK0;
        const float* Wr1 = W + (size_t)(colbase + aRow1) * K + aK0;
        float acc[TM][TN];
#pragma unroll
        for (int m = 0; m < TM; m++)
#pragma unroll
            for (int n = 0; n < TN; n++) acc[m][n] = 0.f;
        for (int k0 = 0; k0 < K; k0 += BK) {
            float4 a0 = *(const float4*)(Xr0 + k0);
            float4 a1 = *(const float4*)(Xr1 + k0);
            float4 b0 = *(const float4*)(Wr0 + k0);
            float4 b1 = *(const float4*)(Wr1 + k0);
            __syncthreads();
            As[(aK0 + 0) * 128 + aRow0] = a0.x; As[(aK0 + 1) * 128 + aRow0] = a0.y;
            As[(aK0 + 2) * 128 + aRow0] = a0.z; As[(aK0 + 3) * 128 + aRow0] = a0.w;
            As[(aK0 + 0) * 128 + aRow1] = a1.x; As[(aK0 + 1) * 128 + aRow1] = a1.y;
            As[(aK0 + 2) * 128 + aRow1] = a1.z; As[(aK0 + 3) * 128 + aRow1] = a1.w;
            Bs[(aK0 + 0) * 128 + aRow0] = b0.x; Bs[(aK0 + 1) * 128 + aRow0] = b0.y;
            Bs[(aK0 + 2) * 128 + aRow0] = b0.z; Bs[(aK0 + 3) * 128 + aRow0] = b0.w;
            Bs[(aK0 + 0) * 128 + aRow1] = b1.x; Bs[(aK0 + 1) * 128 + aRow1] = b1.y;
            Bs[(aK0 + 2) * 128 + aRow1] = b1.z; Bs[(aK0 + 3) * 128 + aRow1] = b1.w;
            __syncthreads();
#pragma unroll
            for (int k = 0; k < BK; k++) {
#pragma unroll
                for (int m = 0; m < TM; m++) {
                    float a = As[k * 128 + ty * TM + m];
#pragma unroll
                    for (int n = 0; n < TN; n++)
                        acc[m][n] = fmaf(a, Bs[k * 128 + tx * TN + n], acc[m][n]);
                }
            }
        }
        int lr0 = (mode == 0) ? (by * NPTS + ty * TM) : (byl * NPTS + ty * TM);
        int col0 = colbase + tx * TN;
        float* Csel = (mode == 0) ? d_h : ((by < 32) ? C0 : d_tmp);
        const float* Rsel = (mode == 1) ? ((by < 32) ? R0 : R1) : nullptr;
#pragma unroll
        for (int m = 0; m < TM; m++) {
            int gr = lr0 + m;
            const float* rr = Rsel ? (Rsel + (size_t)gr * N) : nullptr;
#pragma unroll
            for (int n = 0; n < TN; n++) {
                float vv = fmaxf(acc[m][n], 0.f);
                if (rr) vv += rr[col0 + n];
                Csel[(size_t)gr * N + col0 + n] = vv;
            }
        }
        __syncthreads();
    }
#endif
}

// --------------------------- JV Hungarian (fast) ----------------------------
__device__ __forceinline__ unsigned fkey(float f) {
    unsigned u = __float_as_uint(f);
    return (u & 0x80000000u) ? ~u : (u | 0x80000000u);
}
__device__ __forceinline__ float fuk(unsigned k) {
    k = (k & 0x80000000u) ? (k & 0x7fffffffu) : ~k;
    return __uint_as_float(k);
}

__global__ void lap_kernel() {
    extern __shared__ float csh[];            // [128][128] cost, 64KB
    __shared__ float u_sh[NPTS];
    __shared__ int   roc_sh[NPTS];
    __shared__ int   cor_sh[NPTS];
    __shared__ int   way_sh[NPTS];
    __shared__ int   im_sh[NPTS];
    int b = blockIdx.x, lane = threadIdx.x;

    const float4* src = (const float4*)(d_cost + (size_t)b * NPTS * NPTS);
    float4* dst = (float4*)csh;
    for (int i = lane; i < NPTS * NPTS / 4; i += 32) dst[i] = src[i];
    for (int r = lane; r < NPTS; r += 32) { u_sh[r] = 0.f; cor_sh[r] = -1; }
    __syncwarp();

    float v[4] = {INFINITY, INFINITY, INFINITY, INFINITY};
    int im[4] = {0, 0, 0, 0};
    for (int i = 0; i < NPTS; i++) {
        float4 c4 = *(const float4*)(csh + i * NPTS + 4 * lane);
        float cc[4] = {c4.x, c4.y, c4.z, c4.w};
#pragma unroll
        for (int t = 0; t < 4; t++)
            if (cc[t] < v[t]) { v[t] = cc[t]; im[t] = i; }
    }
#pragma unroll
    for (int t = 0; t < 4; t++) im_sh[4 * lane + t] = im[t];
    __syncwarp();
    if (lane == 0) {
        for (int j = 0; j < NPTS; j++) {
            int i = im_sh[j];
            if (cor_sh[i] < 0) { cor_sh[i] = j; roc_sh[j] = i; }
            else roc_sh[j] = -1;
        }
    }
    __syncwarp();

    for (int i = 0; i < NPTS; i++) {
        if (cor_sh[i] >= 0) continue;
        float dist[4] = {INFINITY, INFINITY, INFINITY, INFINITY};
        int usedm = 0;
        int i0 = i, j0 = -1, jfin = -1;
        float D = 0.f, ui0 = u_sh[i0];
        for (int it = 0; it < NPTS + 2; it++) {
            float4 c4 = *(const float4*)(csh + i0 * NPTS + 4 * lane);
            float cc[4] = {c4.x, c4.y, c4.z, c4.w};
            float best = INFINITY; int jb = 0x7fffffff;
#pragma unroll
            for (int t = 0; t < 4; t++) {
                if (!((usedm >> t) & 1)) {
                    float nd = D + cc[t] - ui0 - v[t];
                    if (nd < dist[t]) { dist[t] = nd; way_sh[4 * lane + t] = j0; }
                    if (dist[t] < best) { best = dist[t]; jb = 4 * lane + t; }
                }
            }
            unsigned key = fkey(best);
            unsigned kmin = __reduce_min_sync(FULLM, key);
            unsigned bal = __ballot_sync(FULLM, key == kmin);
            int srcl = __ffs(bal) - 1;
            int j1 = __shfl_sync(FULLM, jb, srcl);
            D = fuk(kmin);
            int i1 = roc_sh[j1];
            if (i1 < 0) { jfin = j1; break; }
            { int ol = j1 >> 2, ot = j1 & 3; if (lane == ol) usedm |= 1 << ot; }
            i0 = i1; ui0 = u_sh[i0]; j0 = j1;
        }
        __syncwarp();
#pragma unroll
        for (int t = 0; t < 4; t++) {
            if ((usedm >> t) & 1) {
                int j = 4 * lane + t;
                float dd = D - dist[t];
                v[t] -= dd;
                u_sh[roc_sh[j]] += dd;
            }
        }
        if (lane == 0) u_sh[i] += D;
        __syncwarp();
        if (lane == 0) {
            int j = jfin;
            while (way_sh[j] >= 0) { int jp = way_sh[j]; roc_sh[j] = roc_sh[jp]; j = jp; }
            roc_sh[j] = i;
        }
        __syncwarp();
    }
    for (int j = lane; j < NPTS; j += 32)
        d_perm[b * NPTS + roc_sh[j]] = b * NPTS + j;
}

// --------------------------- out1 permutation gather ------------------------
__global__ void gather_kernel(float* __restrict__ out1) {
    int g = blockIdx.x;
    int src = d_perm[g];
    const float4* s = (const float4*)(d_tmp + (size_t)src * DIM);
    float4* d = (float4*)(out1 + (size_t)g * DIM);
    for (int k = threadIdx.x; k < DIM / 4; k += 256) d[k] = s[k];
}

// ------------------------------ launch --------------------------------------
static cudaStream_t g_s2 = nullptr;
static cudaEvent_t g_evF = nullptr, g_evJ = nullptr;

extern "C" void kernel_launch(void* const* d_in, const int* in_sizes, int n_in,
                              void* d_out, int out_size) {
    const float* support = (const float*)d_in[0];
    const float* query   = (const float*)d_in[1];
    const float* W1      = (const float*)d_in[2];   // [1024, 2048]
    const float* W2      = (const float*)d_in[3];   // [2048, 1024]
    float* out0 = (float*)d_out;
    float* out1 = out0 + (size_t)MROWS * DIM;

    if (!g_s2) {   // one-time resource creation (first call is uncaptured)
        cudaStreamCreateWithFlags(&g_s2, cudaStreamNonBlocking);
        cudaEventCreateWithFlags(&g_evF, cudaEventDisableTiming);
        cudaEventCreateWithFlags(&g_evJ, cudaEventDisableTiming);
        cudaFuncSetAttribute(lap_kernel, cudaFuncAttributeMaxDynamicSharedMemorySize, 65536);
        cudaFuncSetAttribute(tgemm_kernel, cudaFuncAttributeMaxDynamicSharedMemorySize, TG_SMEM);
    }

    // fork: GEMM chain (independent of matching) runs on s2 concurrently
    cudaEventRecord(g_evF, 0);
    cudaStreamWaitEvent(g_s2, g_evF, 0);

    // stream 0: matching path (norms fused into cost)
    cost_kernel<<<dim3(4, BATCH), 256>>>(support, query);
    lap_kernel<<<BATCH, 32, 65536>>>();

    // stream s2: MLP, both branches merged per layer (perm commutes with MLP)
    tgemm_kernel<<<dim3(HID / BNT, 2 * BATCH), 256, TG_SMEM, g_s2>>>(
        support, query, W1, nullptr, nullptr, nullptr, HID, DIM, 0);
    tgemm_kernel<<<dim3(DIM / BNT, 2 * BATCH), 256, TG_SMEM, g_s2>>>(
        nullptr, nullptr, W2, out0, support, query, DIM, HID, 1);

    // join, then permute out1
    cudaEventRecord(g_evJ, g_s2);
    cudaStreamWaitEvent(0, g_evJ, 0);
    gather_kernel<<<MROWS, 256>>>(out1);
}

// round 11
// speedup vs baseline: 9.1028x; 1.0493x over previous
#include <cuda_runtime.h>
#include <math.h>
#include <stdint.h>

#define BATCH 32
#define NPTS  128
#define DIM   2048
#define HID   1024
#define MROWS (BATCH * NPTS)   // 4096
#define KC    32               // K floats per smem chunk (= 128B SW128 atom row)
#define BNT   256              // GEMM N tile
#define FULLM 0xffffffffu

// tcgen05 / f32x2 only exist in the sm_103a (arch-specific) compilation pass.
#ifdef __CUDA_ARCH_FEAT_SM103_ALL
#define HAS_TCGEN05 1
#endif

// ------------------------------ scratch ------------------------------------
__device__ float d_cost[BATCH * NPTS * NPTS];
__device__ int   d_perm[MROWS];                 // d_perm[g] = global src row of out1 row g
__device__ float d_h[2u * MROWS * HID];         // hidden acts: rows 0..4095 support, 4096..8191 query
__device__ float d_tmp[(size_t)MROWS * DIM];    // query + mlp(query), unpermuted

// ------------------------------ PTX helpers ---------------------------------
__device__ __forceinline__ uint32_t smem_u32(const void* p) {
    uint32_t a;
    asm("{ .reg .u64 t; cvta.to.shared.u64 t, %1; cvt.u32.u64 %0, t; }"
        : "=r"(a) : "l"(p));
    return a;
}
#define SW128(o) ((o) ^ (((o) >> 3) & 0x70))

#ifdef HAS_TCGEN05
__device__ __forceinline__ float to_tf32(float x) {
    float r; asm("cvt.rna.tf32.f32 %0, %1;" : "=f"(r) : "f"(x)); return r;
}
#define TCGEN05_ALLOC(smem_addr, nCols) \
    asm volatile("tcgen05.alloc.cta_group::1.sync.aligned.shared::cta.b32 [%0], %1;" \
        :: "r"((uint32_t)(smem_addr)), "r"((uint32_t)(nCols)) : "memory")
#define TCGEN05_DEALLOC(tmem_addr, nCols) \
    asm volatile("tcgen05.dealloc.cta_group::1.sync.aligned.b32 %0, %1;" \
        :: "r"(tmem_addr), "r"((uint32_t)(nCols)))
#define TCGEN05_RELINQUISH() \
    asm volatile("tcgen05.relinquish_alloc_permit.cta_group::1.sync.aligned;")
#define TCGEN05_COMMIT(mbar) \
    asm volatile("tcgen05.commit.cta_group::1.mbarrier::arrive::one.shared::cluster.b64 [%0];" \
        :: "r"((uint32_t)(mbar)) : "memory")
#define TCGEN05_FENCE_AFTER() \
    asm volatile("tcgen05.fence::after_thread_sync;" ::: "memory")
#define TCGEN05_FENCE_BEFORE() \
    asm volatile("tcgen05.fence::before_thread_sync;" ::: "memory")
#define TCGEN05_WAIT_LD() \
    asm volatile("tcgen05.wait::ld.sync.aligned;" ::: "memory")
#define TCGEN05_LD_32X32B_X16(r, tmem_addr) \
    asm volatile("tcgen05.ld.sync.aligned.32x32b.x16.b32 " \
        "{%0, %1, %2, %3, %4, %5, %6, %7, %8, %9, %10, %11, %12, %13, %14, %15}, [%16];" \
        : "=r"((r)[0]), "=r"((r)[1]), "=r"((r)[2]), "=r"((r)[3]), \
          "=r"((r)[4]), "=r"((r)[5]), "=r"((r)[6]), "=r"((r)[7]), \
          "=r"((r)[8]), "=r"((r)[9]), "=r"((r)[10]), "=r"((r)[11]), \
          "=r"((r)[12]), "=r"((r)[13]), "=r"((r)[14]), "=r"((r)[15]) \
        : "r"(tmem_addr))
#define MBARRIER_INIT(mbar, count) \
    asm volatile("mbarrier.init.shared.b64 [%0], %1;" \
        :: "r"((uint32_t)(mbar)), "r"((uint32_t)(count)) : "memory")
#define MBARRIER_WAIT_PARITY(mbar, parity) do { \
    uint32_t _m = (uint32_t)(mbar); uint32_t _p = (uint32_t)(parity); uint32_t _d; \
    asm volatile("{\n\t.reg .pred p;\n\t" \
        "mbarrier.try_wait.parity.acquire.cta.shared::cta.b64 p, [%1], %2;\n\t" \
        "selp.b32 %0, 1, 0, p;\n\t}" : "=r"(_d) : "r"(_m), "r"(_p) : "memory"); \
    if (!_d) { \
        asm volatile("{\n\t.reg .pred P1;\n\t" \
            "WL_%=:\n\t" \
            "mbarrier.try_wait.parity.acquire.cta.shared::cta.b64 P1, [%0], %1, 0x989680;\n\t" \
            "@P1 bra.uni WD_%=;\n\t" \
            "bra.uni WL_%=;\n\t" \
            "WD_%=:\n\t}" :: "r"(_m), "r"(_p) : "memory"); \
    } \
} while (0)

__device__ __forceinline__ void mma_tf32_ss(uint32_t d, uint64_t ad, uint64_t bd,
                                            uint32_t idesc, int acc) {
    asm volatile("{\n\t.reg .pred p;\n\t"
        "setp.ne.u32 p, %4, 0;\n\t"
        "tcgen05.mma.cta_group::1.kind::tf32 [%0], %1, %2, %3, {%5, %5, %5, %5}, p;\n\t"
        "}" :: "r"(d), "l"(ad), "l"(bd), "r"(idesc), "r"(acc), "r"(0u) : "memory");
}
// idesc: c=F32(1<<4), a=TF32(2<<7), b=TF32(2<<10), N=256(32<<17), M=128(8<<24)
#define IDESC_TF32 ((8u << 24) | ((BNT / 8u) << 17) | (2u << 10) | (2u << 7) | (1u << 4))

__device__ __forceinline__ uint64_t make_desc_sw128(uint32_t addr) {
    return ((uint64_t)2 << 61) | ((uint64_t)1 << 46) | ((uint64_t)64 << 32)
         | ((uint64_t)1 << 16) | ((addr >> 4) & 0x3FFF);
}

__device__ __forceinline__ void fma2(unsigned long long& d,
                                     unsigned long long a, unsigned long long b) {
    asm("fma.rn.f32x2 %0, %1, %2, %0;" : "+l"(d) : "l"(a), "l"(b));
}
#endif // HAS_TCGEN05

// ------------------------- cost (fp32) + fused norms -------------------------
// grid (4, BATCH): 128x32 output tile, K=2048. Norms accumulated on the fly
// from the streamed rows (4-lane shfl reduce), so no separate norm kernel.
__global__ void __launch_bounds__(256) cost_kernel(const float* __restrict__ S,
                                                   const float* __restrict__ Q) {
    constexpr int BN = 32, TM = 4, TN = 4;
    __shared__ float2 As2[8][NPTS];
    __shared__ float2 Bs2[8][BN];
    __shared__ float ns_sh[NPTS];
    __shared__ float nq_sh[BN];
    int b = blockIdx.y, cb = blockIdx.x;
    const float* Sb = S + (size_t)b * NPTS * DIM;
    const float* Qb = Q + (size_t)b * NPTS * DIM + (size_t)cb * BN * DIM;
    int tid = threadIdx.x;
    int aRow0 = tid >> 2, aK0 = (tid & 3) << 2;
    int aRow1 = aRow0 + 64;
    const float* Sr0 = Sb + (size_t)aRow0 * DIM + aK0;
    const float* Sr1 = Sb + (size_t)aRow1 * DIM + aK0;
    int bRow = tid >> 2;
    const float* Qr = Qb + (size_t)(bRow & 31) * DIM + aK0;
    int tx = tid & 7, ty = tid >> 3;
    int kk0 = aK0 >> 1;
    float sn0 = 0.f, sn1 = 0.f, qn = 0.f;

#ifdef HAS_TCGEN05
    unsigned long long acc2[TM][TN];
#pragma unroll
    for (int m = 0; m < TM; m++)
#pragma unroll
        for (int n = 0; n < TN; n++) acc2[m][n] = 0ull;

    for (int k0 = 0; k0 < DIM; k0 += 16) {
        float4 a0 = *(const float4*)(Sr0 + k0);
        float4 a1 = *(const float4*)(Sr1 + k0);
        float4 b0 = (bRow < 32) ? *(const float4*)(Qr + k0) : make_float4(0, 0, 0, 0);
        sn0 = fmaf(a0.x, a0.x, sn0); sn0 = fmaf(a0.y, a0.y, sn0);
        sn0 = fmaf(a0.z, a0.z, sn0); sn0 = fmaf(a0.w, a0.w, sn0);
        sn1 = fmaf(a1.x, a1.x, sn1); sn1 = fmaf(a1.y, a1.y, sn1);
        sn1 = fmaf(a1.z, a1.z, sn1); sn1 = fmaf(a1.w, a1.w, sn1);
        qn  = fmaf(b0.x, b0.x, qn);  qn  = fmaf(b0.y, b0.y, qn);
        qn  = fmaf(b0.z, b0.z, qn);  qn  = fmaf(b0.w, b0.w, qn);
        __syncthreads();
        As2[kk0][aRow0] = make_float2(a0.x, a0.y);
        As2[kk0 + 1][aRow0] = make_float2(a0.z, a0.w);
        As2[kk0][aRow1] = make_float2(a1.x, a1.y);
        As2[kk0 + 1][aRow1] = make_float2(a1.z, a1.w);
        if (bRow < 32) {
            Bs2[kk0][bRow] = make_float2(b0.x, b0.y);
            Bs2[kk0 + 1][bRow] = make_float2(b0.z, b0.w);
        }
        __syncthreads();
#pragma unroll
        for (int kk = 0; kk < 8; kk++) {
            unsigned long long a2[TM], b2[TN];
#pragma unroll
            for (int m = 0; m < TM; m++)
                a2[m] = *(const unsigned long long*)&As2[kk][ty * TM + m];
#pragma unroll
            for (int n = 0; n < TN; n++)
                b2[n] = *(const unsigned long long*)&Bs2[kk][tx * TN + n];
#pragma unroll
            for (int m = 0; m < TM; m++)
#pragma unroll
                for (int n = 0; n < TN; n++) fma2(acc2[m][n], a2[m], b2[n]);
        }
    }
    // 4-lane reduce (threads 4r..4r+3 share a row)
    sn0 += __shfl_xor_sync(FULLM, sn0, 1); sn0 += __shfl_xor_sync(FULLM, sn0, 2);
    sn1 += __shfl_xor_sync(FULLM, sn1, 1); sn1 += __shfl_xor_sync(FULLM, sn1, 2);
    qn  += __shfl_xor_sync(FULLM, qn, 1);  qn  += __shfl_xor_sync(FULLM, qn, 2);
    if ((tid & 3) == 0) {
        ns_sh[aRow0] = sn0; ns_sh[aRow1] = sn1;
        if (bRow < 32) nq_sh[bRow] = qn;
    }
    __syncthreads();
#pragma unroll
    for (int m = 0; m < TM; m++) {
        int r = ty * TM + m;
        float ni = sqrtf(ns_sh[r]);
#pragma unroll
        for (int n = 0; n < TN; n++) {
            int cl = tx * TN + n;
            float nj = sqrtf(nq_sh[cl]);
            float lo = __uint_as_float((unsigned)(acc2[m][n] & 0xffffffffull));
            float hi = __uint_as_float((unsigned)(acc2[m][n] >> 32));
            d_cost[(size_t)b * NPTS * NPTS + r * NPTS + cb * BN + cl] =
                1.0f - (lo + hi) / (ni * nj);
        }
    }
#else
    float acc[TM][TN];
#pragma unroll
    for (int m = 0; m < TM; m++)
#pragma unroll
        for (int n = 0; n < TN; n++) acc[m][n] = 0.f;
    for (int k0 = 0; k0 < DIM; k0 += 16) {
        float4 a0 = *(const float4*)(Sr0 + k0);
        float4 a1 = *(const float4*)(Sr1 + k0);
        float4 b0 = (bRow < 32) ? *(const float4*)(Qr + k0) : make_float4(0, 0, 0, 0);
        sn0 = fmaf(a0.x, a0.x, sn0); sn0 = fmaf(a0.y, a0.y, sn0);
        sn0 = fmaf(a0.z, a0.z, sn0); sn0 = fmaf(a0.w, a0.w, sn0);
        sn1 = fmaf(a1.x, a1.x, sn1); sn1 = fmaf(a1.y, a1.y, sn1);
        sn1 = fmaf(a1.z, a1.z, sn1); sn1 = fmaf(a1.w, a1.w, sn1);
        qn  = fmaf(b0.x, b0.x, qn);  qn  = fmaf(b0.y, b0.y, qn);
        qn  = fmaf(b0.z, b0.z, qn);  qn  = fmaf(b0.w, b0.w, qn);
        __syncthreads();
        As2[kk0][aRow0] = make_float2(a0.x, a0.y);
        As2[kk0 + 1][aRow0] = make_float2(a0.z, a0.w);
        As2[kk0][aRow1] = make_float2(a1.x, a1.y);
        As2[kk0 + 1][aRow1] = make_float2(a1.z, a1.w);
        if (bRow < 32) {
            Bs2[kk0][bRow] = make_float2(b0.x, b0.y);
            Bs2[kk0 + 1][bRow] = make_float2(b0.z, b0.w);
        }
        __syncthreads();
#pragma unroll
        for (int kk = 0; kk < 8; kk++) {
#pragma unroll
            for (int m = 0; m < TM; m++) {
                float2 a = As2[kk][ty * TM + m];
#pragma unroll
                for (int n = 0; n < TN; n++) {
                    float2 bb = Bs2[kk][tx * TN + n];
                    acc[m][n] = fmaf(a.x, bb.x, acc[m][n]);
                    acc[m][n] = fmaf(a.y, bb.y, acc[m][n]);
                }
            }
        }
    }
    sn0 += __shfl_xor_sync(FULLM, sn0, 1); sn0 += __shfl_xor_sync(FULLM, sn0, 2);
    sn1 += __shfl_xor_sync(FULLM, sn1, 1); sn1 += __shfl_xor_sync(FULLM, sn1, 2);
    qn  += __shfl_xor_sync(FULLM, qn, 1);  qn  += __shfl_xor_sync(FULLM, qn, 2);
    if ((tid & 3) == 0) {
        ns_sh[aRow0] = sn0; ns_sh[aRow1] = sn1;
        if (bRow < 32) nq_sh[bRow] = qn;
    }
    __syncthreads();
#pragma unroll
    for (int m = 0; m < TM; m++) {
        int r = ty * TM + m;
        float ni = sqrtf(ns_sh[r]);
#pragma unroll
        for (int n = 0; n < TN; n++) {
            int cl = tx * TN + n;
            float nj = sqrtf(nq_sh[cl]);
            d_cost[(size_t)b * NPTS * NPTS + r * NPTS + cb * BN + cl] =
                1.0f - acc[m][n] / (ni * nj);
        }
    }
#endif
}

// ------------------------- merged MLP GEMM (128 x 256 tile) ------------------
// mode 0 (layer 1): X = [support; query] (A0/A1 split by by<32), C = d_h, relu.
// mode 1 (layer 2): X = d_h, C = by<32 ? C0(out0) : d_tmp,
//                   resid = by<32 ? R0(support) : R1(query), relu + resid.
// tcgen05 path: SS tf32 MMA N=256, 2 smem stages, alloc-permit relinquished
// immediately (so 2 CTAs/SM can co-allocate TMEM), register double-buffer
// prefetch of the next K-chunk.
#define TG_SMEM (1024 + 2 * 49152)
__global__ void __launch_bounds__(256, 2)
tgemm_kernel(const float* __restrict__ A0, const float* __restrict__ A1,
             const float* __restrict__ W, float* __restrict__ C0,
             const float* __restrict__ R0, const float* __restrict__ R1,
             int N, int K, int mode) {
    extern __shared__ char smem[];
    int tid = threadIdx.x;
    int bx = blockIdx.x, by = blockIdx.y;
    int byl = by & 31;                 // branch-local tile row (mode 1)
    const float* Abase;
    if (mode == 0)
        Abase = (by < 32) ? (A0 + (size_t)by * NPTS * K)
                          : (A1 + (size_t)(by - 32) * NPTS * K);
    else
        Abase = d_h + (size_t)by * NPTS * K;

#ifdef HAS_TCGEN05
    uint32_t sb = smem_u32(smem);
    int wid = tid >> 5, lane = tid & 31;

    if (wid == 0) {
        TCGEN05_ALLOC(sb, BNT);
        TCGEN05_RELINQUISH();          // release permit NOW so the co-resident
    }                                   // CTA's alloc isn't blocked (occ 2)
    if (tid == 0) { MBARRIER_INIT(sb + 8, 1); MBARRIER_INIT(sb + 16, 1); }
    __syncthreads();
    uint32_t tmem;
    asm volatile("ld.shared.b32 %0, [%1];" : "=r"(tmem) : "r"(sb));

    // slot structure: slot i covers row (tid>>3)+32*i, kgroup tid&7 (float4).
    // swizzled offset stride per i is exactly +4096 (r&7 invariant under +32).
    int r0 = tid >> 3, kg = tid & 7;
    const float* ap0 = Abase + (size_t)r0 * K + kg * 4;
    const float* bp0 = W + (size_t)(bx * BNT + r0) * K + kg * 4;
    uint32_t soff0 = SW128((uint32_t)(r0 * 128 + kg * 16));
    size_t astep = (size_t)32 * K;

    uint64_t adesc[2] = { make_desc_sw128(sb + 1024),
                          make_desc_sw128(sb + 1024 + 49152) };
    uint64_t bdesc[2] = { make_desc_sw128(sb + 1024 + 16384),
                          make_desc_sw128(sb + 1024 + 49152 + 16384) };

    const int NCH = K / KC;
    float4 a4[4], b4[8], an[4], bn[8];
#pragma unroll
    for (int i = 0; i < 4; i++) a4[i] = *(const float4*)(ap0 + i * astep);
#pragma unroll
    for (int i = 0; i < 8; i++) b4[i] = *(const float4*)(bp0 + i * astep);
    for (int c = 0; c < NCH; c++) {
        int s = c & 1;
        uint32_t stg = 1024 + (uint32_t)s * 49152;
        if (c + 1 < NCH) {               // prefetch next chunk before any wait
            const float* apn = ap0 + (size_t)(c + 1) * KC;
            const float* bpn = bp0 + (size_t)(c + 1) * KC;
#pragma unroll
            for (int i = 0; i < 4; i++) an[i] = *(const float4*)(apn + i * astep);
#pragma unroll
            for (int i = 0; i < 8; i++) bn[i] = *(const float4*)(bpn + i * astep);
        }
        if (c >= 2) MBARRIER_WAIT_PARITY(sb + 8 + 8 * s, ((c >> 1) - 1) & 1);
#pragma unroll
        for (int i = 0; i < 4; i++) {
            float4 t;
            t.x = to_tf32(a4[i].x); t.y = to_tf32(a4[i].y);
            t.z = to_tf32(a4[i].z); t.w = to_tf32(a4[i].w);
            *(float4*)(smem + stg + soff0 + i * 4096u) = t;
        }
#pragma unroll
        for (int i = 0; i < 8; i++) {
            float4 t;
            t.x = to_tf32(b4[i].x); t.y = to_tf32(b4[i].y);
            t.z = to_tf32(b4[i].z); t.w = to_tf32(b4[i].w);
            *(float4*)(smem + stg + 16384 + soff0 + i * 4096u) = t;
        }
        __syncthreads();
        if (tid == 0) {
            asm volatile("fence.proxy.async.shared::cta;" ::: "memory");
#pragma unroll
            for (int k = 0; k < 4; k++)   // 4 x K=8 MMAs cover the 32-float chunk
                mma_tf32_ss(tmem, adesc[s] + k * 2, bdesc[s] + k * 2, IDESC_TF32, (c | k) != 0);
            TCGEN05_COMMIT(sb + 8 + 8 * s);
        }
#pragma unroll
        for (int i = 0; i < 4; i++) a4[i] = an[i];
#pragma unroll
        for (int i = 0; i < 8; i++) b4[i] = bn[i];
    }
    MBARRIER_WAIT_PARITY(sb + 8 + 8 * ((NCH - 1) & 1), ((NCH - 1) >> 1) & 1);
    TCGEN05_FENCE_AFTER();

    // ------------------ epilogue: 16 groups of 16 columns ------------------
    float* St = (float*)(smem + 1024);     // reuse dead stage-0 buffer
    int wrow = tid >> 1, wc0 = (tid & 1) * 8;
    float* Cb; const float* rres = nullptr;
    if (mode == 0) {
        Cb = d_h + (size_t)(by * NPTS + wrow) * N;
    } else {
        size_t lr = (size_t)(byl * NPTS + wrow);
        Cb = ((by < 32) ? C0 : d_tmp) + lr * N;
        rres = ((by < 32) ? R0 : R1) + lr * N;
    }
    for (int g = 0; g < BNT / 16; g++) {
        if (tid < 128) {
            uint32_t r16[16];
            TCGEN05_LD_32X32B_X16(r16, tmem + g * 16);
            TCGEN05_WAIT_LD();
            int row = wid * 32 + lane;
#pragma unroll
            for (int cc = 0; cc < 16; cc++)
                St[row * 17 + cc] = __uint_as_float(r16[cc]);
        }
        __syncthreads();
        {
            int col = bx * BNT + g * 16 + wc0;
            float o[8];
#pragma unroll
            for (int cc = 0; cc < 8; cc++) {
                float f = fmaxf(St[wrow * 17 + wc0 + cc], 0.f);
                if (mode == 1) f += rres[col + cc];
                o[cc] = f;
            }
            *(float4*)(Cb + col)     = make_float4(o[0], o[1], o[2], o[3]);
            *(float4*)(Cb + col + 4) = make_float4(o[4], o[5], o[6], o[7]);
        }
        __syncthreads();
    }
    TCGEN05_FENCE_BEFORE();
    if (wid == 0) TCGEN05_DEALLOC(tmem, BNT);

#else  // ---------------- FFMA fallback (generic PTX pass; never runs) -------
    constexpr int BK = 16, TM = 8, TN = 8;
    float* As = (float*)smem;
    float* Bs = (float*)(smem + 8192);
    int aRow0 = tid >> 2, aK0 = (tid & 3) << 2;
    int aRow1 = aRow0 + 64;
    const float* Xr0 = Abase + (size_t)aRow0 * K + aK0;
    const float* Xr1 = Abase + (size_t)aRow1 * K + aK0;
    int tx = tid & 15, ty = tid >> 4;
    for (int nh = 0; nh < BNT / 128; nh++) {
        int colbase = bx * BNT + nh * 128;
        const float* Wr0 = W + (size_t)(colbase + aRow0) * K + aK0;
        const float* Wr1 = W + (size_t)(colbase + aRow1) * K + aK0;
        float acc[TM][TN];
#pragma unroll
        for (int m = 0; m < TM; m++)
#pragma unroll
            for (int n = 0; n < TN; n++) acc[m][n] = 0.f;
        for (int k0 = 0; k0 < K; k0 += BK) {
            float4 a0 = *(const float4*)(Xr0 + k0);
            float4 a1 = *(const float4*)(Xr1 + k0);
            float4 b0 = *(const float4*)(Wr0 + k0);
            float4 b1 = *(const float4*)(Wr1 + k0);
            __syncthreads();
            As[(aK0 + 0) * 128 + aRow0] = a0.x; As[(aK0 + 1) * 128 + aRow0] = a0.y;
            As[(aK0 + 2) * 128 + aRow0] = a0.z; As[(aK0 + 3) * 128 + aRow0] = a0.w;
            As[(aK0 + 0) * 128 + aRow1] = a1.x; As[(aK0 + 1) * 128 + aRow1] = a1.y;
            As[(aK0 + 2) * 128 + aRow1] = a1.z; As[(aK0 + 3) * 128 + aRow1] = a1.w;
            Bs[(aK0 + 0) * 128 + aRow0] = b0.x; Bs[(aK0 + 1) * 128 + aRow0] = b0.y;
            Bs[(aK0 + 2) * 128 + aRow0] = b0.z; Bs[(aK0 + 3) * 128 + aRow0] = b0.w;
            Bs[(aK0 + 0) * 128 + aRow1] = b1.x; Bs[(aK0 + 1) * 128 + aRow1] = b1.y;
            Bs[(aK0 + 2) * 128 + aRow1] = b1.z; Bs[(aK0 + 3) * 128 + aRow1] = b1.w;
            __syncthreads();
#pragma unroll
            for (int k = 0; k < BK; k++) {
#pragma unroll
                for (int m = 0; m < TM; m++) {
                    float a = As[k * 128 + ty * TM + m];
#pragma unroll
                    for (int n = 0; n < TN; n++)
                        acc[m][n] = fmaf(a, Bs[k * 128 + tx * TN + n], acc[m][n]);
                }
            }
        }
        int lr0 = (mode == 0) ? (by * NPTS + ty * TM) : (byl * NPTS + ty * TM);
        int col0 = colbase + tx * TN;
        float* Csel = (mode == 0) ? d_h : ((by < 32) ? C0 : d_tmp);
        const float* Rsel = (mode == 1) ? ((by < 32) ? R0 : R1) : nullptr;
#pragma unroll
        for (int m = 0; m < TM; m++) {
            int gr = lr0 + m;
            const float* rr = Rsel ? (Rsel + (size_t)gr * N) : nullptr;
#pragma unroll
            for (int n = 0; n < TN; n++) {
                float vv = fmaxf(acc[m][n], 0.f);
                if (rr) vv += rr[col0 + n];
                Csel[(size_t)gr * N + col0 + n] = vv;
            }
        }
        __syncthreads();
    }
#endif
}

// --------------------------- JV Hungarian (fast) ----------------------------
__device__ __forceinline__ unsigned fkey(float f) {
    unsigned u = __float_as_uint(f);
    return (u & 0x80000000u) ? ~u : (u | 0x80000000u);
}
__device__ __forceinline__ float fuk(unsigned k) {
    k = (k & 0x80000000u) ? (k & 0x7fffffffu) : ~k;
    return __uint_as_float(k);
}

__global__ void lap_kernel() {
    extern __shared__ float csh[];            // [128][128] cost, 64KB
    __shared__ float u_sh[NPTS];
    __shared__ int   roc_sh[NPTS];
    __shared__ int   cor_sh[NPTS];
    __shared__ int   way_sh[NPTS];
    __shared__ int   im_sh[NPTS];
    int b = blockIdx.x, lane = threadIdx.x;

    const float4* src = (const float4*)(d_cost + (size_t)b * NPTS * NPTS);
    float4* dst = (float4*)csh;
    for (int i = lane; i < NPTS * NPTS / 4; i += 32) dst[i] = src[i];
    for (int r = lane; r < NPTS; r += 32) { u_sh[r] = 0.f; cor_sh[r] = -1; }
    __syncwarp();

    float v[4] = {INFINITY, INFINITY, INFINITY, INFINITY};
    int im[4] = {0, 0, 0, 0};
    for (int i = 0; i < NPTS; i++) {
        float4 c4 = *(const float4*)(csh + i * NPTS + 4 * lane);
        float cc[4] = {c4.x, c4.y, c4.z, c4.w};
#pragma unroll
        for (int t = 0; t < 4; t++)
            if (cc[t] < v[t]) { v[t] = cc[t]; im[t] = i; }
    }
#pragma unroll
    for (int t = 0; t < 4; t++) im_sh[4 * lane + t] = im[t];
    __syncwarp();
    if (lane == 0) {
        for (int j = 0; j < NPTS; j++) {
            int i = im_sh[j];
            if (cor_sh[i] < 0) { cor_sh[i] = j; roc_sh[j] = i; }
            else roc_sh[j] = -1;
        }
    }
    __syncwarp();

    for (int i = 0; i < NPTS; i++) {
        if (cor_sh[i] >= 0) continue;
        float dist[4] = {INFINITY, INFINITY, INFINITY, INFINITY};
        int usedm = 0;
        int i0 = i, j0 = -1, jfin = -1;
        float D = 0.f, ui0 = u_sh[i0];
        for (int it = 0; it < NPTS + 2; it++) {
            float4 c4 = *(const float4*)(csh + i0 * NPTS + 4 * lane);
            float cc[4] = {c4.x, c4.y, c4.z, c4.w};
            float best = INFINITY; int jb = 0x7fffffff;
#pragma unroll
            for (int t = 0; t < 4; t++) {
                if (!((usedm >> t) & 1)) {
                    float nd = D + cc[t] - ui0 - v[t];
                    if (nd < dist[t]) { dist[t] = nd; way_sh[4 * lane + t] = j0; }
                    if (dist[t] < best) { best = dist[t]; jb = 4 * lane + t; }
                }
            }
            unsigned key = fkey(best);
            unsigned kmin = __reduce_min_sync(FULLM, key);
            unsigned bal = __ballot_sync(FULLM, key == kmin);
            int srcl = __ffs(bal) - 1;
            int j1 = __shfl_sync(FULLM, jb, srcl);
            D = fuk(kmin);
            int i1 = roc_sh[j1];
            if (i1 < 0) { jfin = j1; break; }
            { int ol = j1 >> 2, ot = j1 & 3; if (lane == ol) usedm |= 1 << ot; }
            i0 = i1; ui0 = u_sh[i0]; j0 = j1;
        }
        __syncwarp();
#pragma unroll
        for (int t = 0; t < 4; t++) {
            if ((usedm >> t) & 1) {
                int j = 4 * lane + t;
                float dd = D - dist[t];
                v[t] -= dd;
                u_sh[roc_sh[j]] += dd;
            }
        }
        if (lane == 0) u_sh[i] += D;
        __syncwarp();
        if (lane == 0) {
            int j = jfin;
            while (way_sh[j] >= 0) { int jp = way_sh[j]; roc_sh[j] = roc_sh[jp]; j = jp; }
            roc_sh[j] = i;
        }
        __syncwarp();
    }
    for (int j = lane; j < NPTS; j += 32)
        d_perm[b * NPTS + roc_sh[j]] = b * NPTS + j;
}

// --------------------------- out1 permutation gather ------------------------
__global__ void gather_kernel(float* __restrict__ out1) {
    int g = blockIdx.x;
    int src = d_perm[g];
    const float4* s = (const float4*)(d_tmp + (size_t)src * DIM);
    float4* d = (float4*)(out1 + (size_t)g * DIM);
    for (int k = threadIdx.x; k < DIM / 4; k += 256) d[k] = s[k];
}

// ------------------------------ launch --------------------------------------
static cudaStream_t g_s2 = nullptr;
static cudaEvent_t g_evF = nullptr, g_evJ = nullptr;

extern "C" void kernel_launch(void* const* d_in, const int* in_sizes, int n_in,
                              void* d_out, int out_size) {
    const float* support = (const float*)d_in[0];
    const float* query   = (const float*)d_in[1];
    const float* W1      = (const float*)d_in[2];   // [1024, 2048]
    const float* W2      = (const float*)d_in[3];   // [2048, 1024]
    float* out0 = (float*)d_out;
    float* out1 = out0 + (size_t)MROWS * DIM;

    if (!g_s2) {   // one-time resource creation (first call is uncaptured)
        cudaStreamCreateWithFlags(&g_s2, cudaStreamNonBlocking);
        cudaEventCreateWithFlags(&g_evF, cudaEventDisableTiming);
        cudaEventCreateWithFlags(&g_evJ, cudaEventDisableTiming);
        cudaFuncSetAttribute(lap_kernel, cudaFuncAttributeMaxDynamicSharedMemorySize, 65536);
        cudaFuncSetAttribute(tgemm_kernel, cudaFuncAttributeMaxDynamicSharedMemorySize, TG_SMEM);
    }

    // fork: GEMM chain (independent of matching) runs on s2 concurrently
    cudaEventRecord(g_evF, 0);
    cudaStreamWaitEvent(g_s2, g_evF, 0);

    // stream 0: matching path (norms fused into cost)
    cost_kernel<<<dim3(4, BATCH), 256>>>(support, query);
    lap_kernel<<<BATCH, 32, 65536>>>();

    // stream s2: MLP, both branches merged per layer (perm commutes with MLP)
    tgemm_kernel<<<dim3(HID / BNT, 2 * BATCH), 256, TG_SMEM, g_s2>>>(
        support, query, W1, nullptr, nullptr, nullptr, HID, DIM, 0);
    tgemm_kernel<<<dim3(DIM / BNT, 2 * BATCH), 256, TG_SMEM, g_s2>>>(
        nullptr, nullptr, W2, out0, support, query, DIM, HID, 1);

    // join, then permute out1
    cudaEventRecord(g_evJ, g_s2);
    cudaStreamWaitEvent(0, g_evJ, 0);
    gather_kernel<<<MROWS, 256>>>(out1);
}